// round 8
// baseline (speedup 1.0000x reference)
#include <cuda_runtime.h>
#include <cuda_bf16.h>
#include <cstdint>

// ---------------------------------------------------------------------------
// SimpleSNN via bf16x6 emulated-fp32 GEMMs on mma.sync (sm_80+ family ISA).
// R6 fix: tensor-core accumulators use truncating (biased) fp32 accumulation;
// the dominant a1*b1 product is drained into RN fp32 master accumulators every
// 32-k chunk (bias ~3e-7); the 5 small correction products (2^-9 scale) keep a
// full tensor chain (bias ~1e-7).
// Chunk order: p0..p4 = a1b2,a2b1,a1b3,a2b2,a3b1 (chunks 0-159), p5 = a1b1
// (chunks 160-191, drained per chunk).
// d_out layout: [ output (B*OUT) | total_spikes (B*H) ]
// ---------------------------------------------------------------------------

#define BDIM 4096
#define INDIM 1024
#define HDIM 2048
#define ODIM 256

__device__ __nv_bfloat16 g_A1h[(size_t)BDIM * 3072];  // x   [a1|a2|a3]
__device__ __nv_bfloat16 g_B1h[(size_t)HDIM * 3072];  // W1  [b1|b2|b3]
__device__ __nv_bfloat16 g_Sh [(size_t)BDIM * HDIM];  // spikes bf16 (exact)
__device__ __nv_bfloat16 g_W2h[(size_t)ODIM * 4096];  // W2  [w1|w2]

// ------------------------------ helpers ------------------------------------
__device__ __forceinline__ uint32_t smem_u32(const void* p) {
    uint32_t a;
    asm("{ .reg .u64 t; cvta.to.shared.u64 t, %1; cvt.u32.u64 %0, t; }" : "=r"(a) : "l"(p));
    return a;
}
#define CP16(dst, src)  asm volatile("cp.async.cg.shared.global [%0], [%1], 16;" :: "r"(dst), "l"(src))
#define CP_COMMIT()     asm volatile("cp.async.commit_group;" ::: "memory")
#define CP_WAIT1()      asm volatile("cp.async.wait_group 1;" ::: "memory")
#define LDSM4(R, a) asm volatile("ldmatrix.sync.aligned.m8n8.x4.shared.b16 {%0,%1,%2,%3}, [%4];" \
    : "=r"((R)[0]), "=r"((R)[1]), "=r"((R)[2]), "=r"((R)[3]) : "r"(a))

__device__ __forceinline__ void mma_bf16(float* c, const uint32_t* a, const uint32_t* b) {
    asm volatile(
        "mma.sync.aligned.m16n8k16.row.col.f32.bf16.bf16.f32 "
        "{%0,%1,%2,%3}, {%4,%5,%6,%7}, {%8,%9}, {%0,%1,%2,%3};"
        : "+f"(c[0]), "+f"(c[1]), "+f"(c[2]), "+f"(c[3])
        : "r"(a[0]), "r"(a[1]), "r"(a[2]), "r"(a[3]), "r"(b[0]), "r"(b[1]));
}

// ------------------------------ split kernels ------------------------------
__global__ void split3_kernel(const float* __restrict__ src, __nv_bfloat16* __restrict__ dst,
                              int total)  // K=1024, dst stride 3072
{
    for (int e = blockIdx.x * blockDim.x + threadIdx.x; e < total; e += gridDim.x * blockDim.x) {
        const int r = e >> 10, k = e & 1023;
        const float a = src[e];
        const __nv_bfloat16 a1 = __float2bfloat16(a);
        const float r1 = a - __bfloat162float(a1);     // exact
        const __nv_bfloat16 a2 = __float2bfloat16(r1);
        const float r2 = r1 - __bfloat162float(a2);    // exact
        const __nv_bfloat16 a3 = __float2bfloat16(r2);
        __nv_bfloat16* d = dst + (size_t)r * 3072;
        d[k] = a1; d[1024 + k] = a2; d[2048 + k] = a3;
    }
}
__global__ void split2_kernel(const float* __restrict__ src, __nv_bfloat16* __restrict__ dst,
                              int total)  // K=2048, dst stride 4096
{
    for (int e = blockIdx.x * blockDim.x + threadIdx.x; e < total; e += gridDim.x * blockDim.x) {
        const int r = e >> 11, k = e & 2047;
        const float a = src[e];
        const __nv_bfloat16 a1 = __float2bfloat16(a);
        const __nv_bfloat16 a2 = __float2bfloat16(a - __bfloat162float(a1));
        __nv_bfloat16* d = dst + (size_t)r * 4096;
        d[k] = a1; d[2048 + k] = a2;
    }
}

// ------------------------------ GEMM1 + LIF --------------------------------
// CTA 128x128, BK=32 bf16, 3-stage cp.async. smem rows: 32 bf16 padded to 80B.
// 192 chunks = 6 products x 32 chunks.
// Product order: A {a1,a2,a1,a2,a3,a1}, B {b2,b1,b3,b2,b1,b1}.
#define G1_CHUNKS 192
#define AST 10240   // 128 rows * 80B per stage

__device__ __forceinline__ void g1_load(uint32_t sA, uint32_t sB, int m0, int n0,
                                        int kt, int st, int tid)
{
    const int p = kt >> 5, cc = kt & 31;
    if (tid < 128) {
        const int sec = (0x021010 >> (p * 4)) & 0xF;            // a: 0,1,0,1,2,0
        const __nv_bfloat16* g = g_A1h + (size_t)(m0 + tid) * 3072 + sec * 1024 + cc * 32;
        const uint32_t d = sA + st * AST + tid * 80;
        CP16(d, g); CP16(d + 16, g + 8); CP16(d + 32, g + 16); CP16(d + 48, g + 24);
    } else {
        const int r = tid - 128;
        const int sec = (0x001201 >> (p * 4)) & 0xF;            // b: 1,0,2,1,0,0
        const __nv_bfloat16* g = g_B1h + (size_t)(n0 + r) * 3072 + sec * 1024 + cc * 32;
        const uint32_t d = sB + st * AST + r * 80;
        CP16(d, g); CP16(d + 16, g + 8); CP16(d + 32, g + 16); CP16(d + 48, g + 24);
    }
}

__global__ __launch_bounds__(256)
void gemm1_lif_kernel(const float* __restrict__ b1, const float* __restrict__ v0,
                      const float* __restrict__ i0, const float* __restrict__ tau_mem,
                      const float* __restrict__ tau_syn, const float* __restrict__ v_thresh,
                      const float* __restrict__ v_reset, const int* __restrict__ tsteps,
                      float* __restrict__ spikes)
{
    extern __shared__ __align__(128) char smem[];
    const uint32_t sA = smem_u32(smem);
    const uint32_t sB = sA + 3 * AST;

    const int tid = threadIdx.x, lane = tid & 31, wid = tid >> 5;
    const int wm = wid >> 2, wn = wid & 3;             // warp tile 64x32
    const int g = lane >> 2, tq = lane & 3;
    const int mi = lane >> 3, r8 = lane & 7;
    const int m0 = blockIdx.y * 128, n0 = blockIdx.x * 128;

    const uint32_t aoff = (uint32_t)(((mi & 1) * 8 + r8) * 80 + (mi >> 1) * 16);
    const uint32_t boff = (uint32_t)(((mi >> 1) * 8 + r8) * 80 + (mi & 1) * 16);

    float mster[4][4][4];   // RN fp32 master accumulators
    float tacc[4][4][4];    // tensor-core temp accumulators
#pragma unroll
    for (int a = 0; a < 4; a++)
#pragma unroll
        for (int b = 0; b < 4; b++)
#pragma unroll
            for (int c = 0; c < 4; c++) { mster[a][b][c] = 0.0f; tacc[a][b][c] = 0.0f; }

    g1_load(sA, sB, m0, n0, 0, 0, tid); CP_COMMIT();
    g1_load(sA, sB, m0, n0, 1, 1, tid); CP_COMMIT();

    for (int kt = 0; kt < G1_CHUNKS; kt++) {
        const int buf = kt % 3;
        CP_WAIT1();
        __syncthreads();
        if (kt + 2 < G1_CHUNKS) g1_load(sA, sB, m0, n0, kt + 2, (kt + 2) % 3, tid);
        CP_COMMIT();

        const uint32_t Ab = sA + buf * AST + (wm * 64) * 80 + aoff;
        const uint32_t Bb = sB + buf * AST + (wn * 32) * 80 + boff;
#pragma unroll
        for (int ks = 0; ks < 2; ks++) {
            uint32_t af[4][4], bfr[2][4];
#pragma unroll
            for (int mt = 0; mt < 4; mt++) LDSM4(af[mt], Ab + mt * 16 * 80 + ks * 32);
#pragma unroll
            for (int np = 0; np < 2; np++) LDSM4(bfr[np], Bb + np * 16 * 80 + ks * 32);
#pragma unroll
            for (int mt = 0; mt < 4; mt++)
#pragma unroll
                for (int nt = 0; nt < 4; nt++)
                    mma_bf16(tacc[mt][nt], af[mt], &bfr[nt >> 1][(nt & 1) * 2]);
        }
        // Drain: once after all corrections (kt==159), then every a1b1 chunk.
        if (kt >= 159) {
#pragma unroll
            for (int a = 0; a < 4; a++)
#pragma unroll
                for (int b = 0; b < 4; b++)
#pragma unroll
                    for (int c = 0; c < 4; c++) {
                        mster[a][b][c] += tacc[a][b][c];
                        tacc[a][b][c] = 0.0f;
                    }
        }
    }
    // C frag: c0=(g,2tq) c1=(g,2tq+1) c2=(g+8,2tq) c3=(g+8,2tq+1)

    // -------------------- fused LIF epilogue --------------------
    const float km  = 1.0f / tau_mem[0];
    const float kss = 1.0f / tau_syn[0];
    const float vth = v_thresh[0];
    const float vre = v_reset[0];
    const int   T   = tsteps[0];
    const float invT = 1.0f / (float)T;

#pragma unroll
    for (int mt = 0; mt < 4; mt++) {
#pragma unroll
        for (int rs = 0; rs < 2; rs++) {
            const int gm = m0 + wm * 64 + mt * 16 + g + rs * 8;
            float cur[8], vv[8], ii[8], cnt[8];
#pragma unroll
            for (int nt = 0; nt < 4; nt++) {
                const int gc = n0 + wn * 32 + nt * 8 + 2 * tq;
                const size_t off = (size_t)gm * HDIM + gc;
                const float2 v2 = *reinterpret_cast<const float2*>(v0 + off);
                const float2 i2 = *reinterpret_cast<const float2*>(i0 + off);
                cur[2 * nt]     = (mster[mt][nt][rs * 2 + 0] + __ldg(b1 + gc))     * invT;
                cur[2 * nt + 1] = (mster[mt][nt][rs * 2 + 1] + __ldg(b1 + gc + 1)) * invT;
                vv[2 * nt] = v2.x; vv[2 * nt + 1] = v2.y;
                ii[2 * nt] = i2.x; ii[2 * nt + 1] = i2.y;
                cnt[2 * nt] = 0.0f; cnt[2 * nt + 1] = 0.0f;
            }
            for (int t = 0; t < T; t++) {
#pragma unroll
                for (int j = 0; j < 8; j++) {
                    ii[j] = ii[j] - kss * ii[j] + cur[j];
                    vv[j] = vv[j] - km  * vv[j] + ii[j];
                    if (vv[j] >= vth) { cnt[j] += 1.0f; vv[j] = vre; }
                }
            }
#pragma unroll
            for (int nt = 0; nt < 4; nt++) {
                const int gc = n0 + wn * 32 + nt * 8 + 2 * tq;
                float2 s2; s2.x = cnt[2 * nt]; s2.y = cnt[2 * nt + 1];
                *reinterpret_cast<float2*>(spikes + (size_t)gm * HDIM + gc) = s2;
                __nv_bfloat162 sb;
                sb.x = __float2bfloat16(cnt[2 * nt]);
                sb.y = __float2bfloat16(cnt[2 * nt + 1]);
                *reinterpret_cast<__nv_bfloat162*>(g_Sh + (size_t)gm * HDIM + gc) = sb;
            }
        }
    }
}

// ------------------------------ GEMM2 --------------------------------------
// out = [s|s] @ [w1|w2]^T + b2. CTA 128x64, BK=32, 3 stages, 128 chunks.
// Tensor-chain bias ~6e-5 on the output: within tolerance, no drains needed.
#define G2_CHUNKS 128
#define BST2 5120   // 64 rows * 80B per stage

__device__ __forceinline__ void g2_load(uint32_t sA, uint32_t sB, int m0, int n0,
                                        int kt, int st, int tid)
{
    if (tid < 128) {
        const __nv_bfloat16* g = g_Sh + (size_t)(m0 + tid) * HDIM + (kt & 63) * 32;
        const uint32_t d = sA + st * AST + tid * 80;
        CP16(d, g); CP16(d + 16, g + 8); CP16(d + 32, g + 16); CP16(d + 48, g + 24);
    } else if (tid < 192) {
        const int r = tid - 128;
        const __nv_bfloat16* g = g_W2h + (size_t)(n0 + r) * 4096 + kt * 32;
        const uint32_t d = sB + st * BST2 + r * 80;
        CP16(d, g); CP16(d + 16, g + 8); CP16(d + 32, g + 16); CP16(d + 48, g + 24);
    }
}

__global__ __launch_bounds__(256)
void gemm2_kernel(const float* __restrict__ b2, float* __restrict__ out)
{
    extern __shared__ __align__(128) char smem2[];
    const uint32_t sA = smem_u32(smem2);
    const uint32_t sB = sA + 3 * AST;

    const int tid = threadIdx.x, lane = tid & 31, wid = tid >> 5;
    const int wm = wid & 3, wn = wid >> 2;             // warp tile 32x32
    const int g = lane >> 2, tq = lane & 3;
    const int mi = lane >> 3, r8 = lane & 7;
    const int m0 = blockIdx.y * 128, n0 = blockIdx.x * 64;

    const uint32_t aoff = (uint32_t)(((mi & 1) * 8 + r8) * 80 + (mi >> 1) * 16);
    const uint32_t boff = (uint32_t)(((mi >> 1) * 8 + r8) * 80 + (mi & 1) * 16);

    float acc[2][4][4];
#pragma unroll
    for (int a = 0; a < 2; a++)
#pragma unroll
        for (int b = 0; b < 4; b++)
#pragma unroll
            for (int c = 0; c < 4; c++) acc[a][b][c] = 0.0f;

    g2_load(sA, sB, m0, n0, 0, 0, tid); CP_COMMIT();
    g2_load(sA, sB, m0, n0, 1, 1, tid); CP_COMMIT();

    for (int kt = 0; kt < G2_CHUNKS; kt++) {
        const int buf = kt % 3;
        CP_WAIT1();
        __syncthreads();
        if (kt + 2 < G2_CHUNKS) g2_load(sA, sB, m0, n0, kt + 2, (kt + 2) % 3, tid);
        CP_COMMIT();

        const uint32_t Ab = sA + buf * AST + (wm * 32) * 80 + aoff;
        const uint32_t Bb = sB + buf * BST2 + (wn * 32) * 80 + boff;
#pragma unroll
        for (int ks = 0; ks < 2; ks++) {
            uint32_t af[2][4], bfr[2][4];
#pragma unroll
            for (int mt = 0; mt < 2; mt++) LDSM4(af[mt], Ab + mt * 16 * 80 + ks * 32);
#pragma unroll
            for (int np = 0; np < 2; np++) LDSM4(bfr[np], Bb + np * 16 * 80 + ks * 32);
#pragma unroll
            for (int mt = 0; mt < 2; mt++)
#pragma unroll
                for (int nt = 0; nt < 4; nt++)
                    mma_bf16(acc[mt][nt], af[mt], &bfr[nt >> 1][(nt & 1) * 2]);
        }
    }

#pragma unroll
    for (int mt = 0; mt < 2; mt++) {
#pragma unroll
        for (int rs = 0; rs < 2; rs++) {
            const int gm = m0 + wm * 32 + mt * 16 + g + rs * 8;
#pragma unroll
            for (int nt = 0; nt < 4; nt++) {
                const int gc = n0 + wn * 32 + nt * 8 + 2 * tq;
                float2 o2;
                o2.x = acc[mt][nt][rs * 2 + 0] + __ldg(b2 + gc);
                o2.y = acc[mt][nt][rs * 2 + 1] + __ldg(b2 + gc + 1);
                *reinterpret_cast<float2*>(out + (size_t)gm * ODIM + gc) = o2;
            }
        }
    }
}

// ---------------------------------------------------------------------------
extern "C" void kernel_launch(void* const* d_in, const int* in_sizes, int n_in,
                              void* d_out, int out_size)
{
    const float* x        = (const float*)d_in[0];
    const float* W1       = (const float*)d_in[1];
    const float* b1       = (const float*)d_in[2];
    const float* W2       = (const float*)d_in[3];
    const float* b2       = (const float*)d_in[4];
    const float* tau_mem  = (const float*)d_in[5];
    const float* tau_syn  = (const float*)d_in[6];
    const float* v_thresh = (const float*)d_in[7];
    const float* v_reset  = (const float*)d_in[8];
    const float* v0       = (const float*)d_in[9];
    const float* i0       = (const float*)d_in[10];
    const int*   tsteps   = (const int*)d_in[11];

    float* out    = (float*)d_out;
    float* spikes = out + (size_t)BDIM * ODIM;

    __nv_bfloat16 *dA1, *dB1, *dW2;
    cudaGetSymbolAddress((void**)&dA1, g_A1h);
    cudaGetSymbolAddress((void**)&dB1, g_B1h);
    cudaGetSymbolAddress((void**)&dW2, g_W2h);

    const int smem1 = 6 * AST;               // 61440
    const int smem2 = 3 * AST + 3 * BST2;    // 46080
    cudaFuncSetAttribute(gemm1_lif_kernel, cudaFuncAttributeMaxDynamicSharedMemorySize, smem1);
    cudaFuncSetAttribute(gemm2_kernel,     cudaFuncAttributeMaxDynamicSharedMemorySize, smem2);

    split3_kernel<<<2048, 256>>>(x,  dA1, BDIM * INDIM);
    split3_kernel<<<1024, 256>>>(W1, dB1, HDIM * INDIM);
    split2_kernel<<<256,  256>>>(W2, dW2, ODIM * HDIM);

    dim3 g1(HDIM / 128, BDIM / 128);   // 16 x 32 = 512 CTAs
    gemm1_lif_kernel<<<g1, 256, smem1>>>(b1, v0, i0, tau_mem, tau_syn,
                                         v_thresh, v_reset, tsteps, spikes);

    dim3 g2(ODIM / 64, BDIM / 128);    // 4 x 32 = 128 CTAs
    gemm2_kernel<<<g2, 256, smem2>>>(b2, out);
}

// round 9
// speedup vs baseline: 1.1667x; 1.1667x over previous
#include <cuda_runtime.h>
#include <cuda_bf16.h>
#include <cstdint>

// ---------------------------------------------------------------------------
// SimpleSNN via bf16x6 emulated-fp32 GEMMs on mma.sync (sm_80+ family ISA).
// Numerics (R8, passing): 6 products; corrections (2^-9 scale) in one tensor
// chain; dominant a1b1 drained into RN fp32 masters every 32-k chunk.
// R9: gemm1 rebuilt for occupancy — 512 threads, 4x4 warp grid, 32x32 warp
// tile (64 accum floats/thread instead of 128; regs ~110 vs 164).
// d_out layout: [ output (B*OUT) | total_spikes (B*H) ]
// ---------------------------------------------------------------------------

#define BDIM 4096
#define INDIM 1024
#define HDIM 2048
#define ODIM 256

__device__ __nv_bfloat16 g_A1h[(size_t)BDIM * 3072];  // x   [a1|a2|a3]
__device__ __nv_bfloat16 g_B1h[(size_t)HDIM * 3072];  // W1  [b1|b2|b3]
__device__ __nv_bfloat16 g_Sh [(size_t)BDIM * HDIM];  // spikes bf16 (exact)
__device__ __nv_bfloat16 g_W2h[(size_t)ODIM * 4096];  // W2  [w1|w2]

// ------------------------------ helpers ------------------------------------
__device__ __forceinline__ uint32_t smem_u32(const void* p) {
    uint32_t a;
    asm("{ .reg .u64 t; cvta.to.shared.u64 t, %1; cvt.u32.u64 %0, t; }" : "=r"(a) : "l"(p));
    return a;
}
#define CP16(dst, src)  asm volatile("cp.async.cg.shared.global [%0], [%1], 16;" :: "r"(dst), "l"(src))
#define CP_COMMIT()     asm volatile("cp.async.commit_group;" ::: "memory")
#define CP_WAIT1()      asm volatile("cp.async.wait_group 1;" ::: "memory")
#define LDSM4(R, a) asm volatile("ldmatrix.sync.aligned.m8n8.x4.shared.b16 {%0,%1,%2,%3}, [%4];" \
    : "=r"((R)[0]), "=r"((R)[1]), "=r"((R)[2]), "=r"((R)[3]) : "r"(a))

__device__ __forceinline__ void mma_bf16(float* c, const uint32_t* a, const uint32_t* b) {
    asm volatile(
        "mma.sync.aligned.m16n8k16.row.col.f32.bf16.bf16.f32 "
        "{%0,%1,%2,%3}, {%4,%5,%6,%7}, {%8,%9}, {%0,%1,%2,%3};"
        : "+f"(c[0]), "+f"(c[1]), "+f"(c[2]), "+f"(c[3])
        : "r"(a[0]), "r"(a[1]), "r"(a[2]), "r"(a[3]), "r"(b[0]), "r"(b[1]));
}

// ------------------------------ split kernels ------------------------------
__global__ void split3_kernel(const float* __restrict__ src, __nv_bfloat16* __restrict__ dst,
                              int total)  // K=1024, dst stride 3072
{
    for (int e = blockIdx.x * blockDim.x + threadIdx.x; e < total; e += gridDim.x * blockDim.x) {
        const int r = e >> 10, k = e & 1023;
        const float a = src[e];
        const __nv_bfloat16 a1 = __float2bfloat16(a);
        const float r1 = a - __bfloat162float(a1);     // exact
        const __nv_bfloat16 a2 = __float2bfloat16(r1);
        const float r2 = r1 - __bfloat162float(a2);    // exact
        const __nv_bfloat16 a3 = __float2bfloat16(r2);
        __nv_bfloat16* d = dst + (size_t)r * 3072;
        d[k] = a1; d[1024 + k] = a2; d[2048 + k] = a3;
    }
}
__global__ void split2_kernel(const float* __restrict__ src, __nv_bfloat16* __restrict__ dst,
                              int total)  // K=2048, dst stride 4096
{
    for (int e = blockIdx.x * blockDim.x + threadIdx.x; e < total; e += gridDim.x * blockDim.x) {
        const int r = e >> 11, k = e & 2047;
        const float a = src[e];
        const __nv_bfloat16 a1 = __float2bfloat16(a);
        const __nv_bfloat16 a2 = __float2bfloat16(a - __bfloat162float(a1));
        __nv_bfloat16* d = dst + (size_t)r * 4096;
        d[k] = a1; d[2048 + k] = a2;
    }
}

// ------------------------------ GEMM1 + LIF --------------------------------
// CTA 128x128, 512 threads, warp grid 4(m)x4(n), warp tile 32x32.
// BK=32 bf16, 3-stage cp.async, 80B-padded rows. 192 chunks = 6 products x 32.
// Product order: A {a1,a2,a1,a2,a3,a1}, B {b2,b1,b3,b2,b1,b1}.
#define G1_CHUNKS 192
#define AST 10240   // 128 rows * 80B per stage

__device__ __forceinline__ void g1_load(uint32_t sA, uint32_t sB, int m0, int n0,
                                        int kt, int st, int tid)
{
    const int p = kt >> 5, cc = kt & 31;
    const int row = (tid >> 1) & 127, part = tid & 1;
    if (tid < 256) {
        const int sec = (0x021010 >> (p * 4)) & 0xF;            // a: 0,1,0,1,2,0
        const __nv_bfloat16* g = g_A1h + (size_t)(m0 + row) * 3072 + sec * 1024 + cc * 32 + part * 16;
        const uint32_t d = sA + st * AST + row * 80 + part * 32;
        CP16(d, g); CP16(d + 16, g + 8);
    } else {
        const int sec = (0x001201 >> (p * 4)) & 0xF;            // b: 1,0,2,1,0,0
        const __nv_bfloat16* g = g_B1h + (size_t)(n0 + row) * 3072 + sec * 1024 + cc * 32 + part * 16;
        const uint32_t d = sB + st * AST + row * 80 + part * 32;
        CP16(d, g); CP16(d + 16, g + 8);
    }
}

__global__ __launch_bounds__(512)
void gemm1_lif_kernel(const float* __restrict__ b1, const float* __restrict__ v0,
                      const float* __restrict__ i0, const float* __restrict__ tau_mem,
                      const float* __restrict__ tau_syn, const float* __restrict__ v_thresh,
                      const float* __restrict__ v_reset, const int* __restrict__ tsteps,
                      float* __restrict__ spikes)
{
    extern __shared__ __align__(128) char smem[];
    const uint32_t sA = smem_u32(smem);
    const uint32_t sB = sA + 3 * AST;

    const int tid = threadIdx.x, lane = tid & 31, wid = tid >> 5;
    const int wm = wid & 3, wn = wid >> 2;             // warp tile 32x32
    const int g = lane >> 2, tq = lane & 3;
    const int mi = lane >> 3, r8 = lane & 7;
    const int m0 = blockIdx.y * 128, n0 = blockIdx.x * 128;

    const uint32_t aoff = (uint32_t)(((mi & 1) * 8 + r8) * 80 + (mi >> 1) * 16);
    const uint32_t boff = (uint32_t)(((mi >> 1) * 8 + r8) * 80 + (mi & 1) * 16);

    float mster[2][4][4];   // RN fp32 master accumulators
    float tacc[2][4][4];    // tensor-core temp accumulators
#pragma unroll
    for (int a = 0; a < 2; a++)
#pragma unroll
        for (int b = 0; b < 4; b++)
#pragma unroll
            for (int c = 0; c < 4; c++) { mster[a][b][c] = 0.0f; tacc[a][b][c] = 0.0f; }

    g1_load(sA, sB, m0, n0, 0, 0, tid); CP_COMMIT();
    g1_load(sA, sB, m0, n0, 1, 1, tid); CP_COMMIT();

    for (int kt = 0; kt < G1_CHUNKS; kt++) {
        const int buf = kt % 3;
        CP_WAIT1();
        __syncthreads();
        if (kt + 2 < G1_CHUNKS) g1_load(sA, sB, m0, n0, kt + 2, (kt + 2) % 3, tid);
        CP_COMMIT();

        const uint32_t Ab = sA + buf * AST + (wm * 32) * 80 + aoff;
        const uint32_t Bb = sB + buf * AST + (wn * 32) * 80 + boff;
#pragma unroll
        for (int ks = 0; ks < 2; ks++) {
            uint32_t af[2][4], bfr[2][4];
#pragma unroll
            for (int mt = 0; mt < 2; mt++) LDSM4(af[mt], Ab + mt * 16 * 80 + ks * 32);
#pragma unroll
            for (int np = 0; np < 2; np++) LDSM4(bfr[np], Bb + np * 16 * 80 + ks * 32);
#pragma unroll
            for (int mt = 0; mt < 2; mt++)
#pragma unroll
                for (int nt = 0; nt < 4; nt++)
                    mma_bf16(tacc[mt][nt], af[mt], &bfr[nt >> 1][(nt & 1) * 2]);
        }
        // Drain: once after all corrections (kt==159), then every a1b1 chunk.
        if (kt >= 159) {
#pragma unroll
            for (int a = 0; a < 2; a++)
#pragma unroll
                for (int b = 0; b < 4; b++)
#pragma unroll
                    for (int c = 0; c < 4; c++) {
                        mster[a][b][c] += tacc[a][b][c];
                        tacc[a][b][c] = 0.0f;
                    }
        }
    }
    // C frag: c0=(g,2tq) c1=(g,2tq+1) c2=(g+8,2tq) c3=(g+8,2tq+1)

    // -------------------- fused LIF epilogue --------------------
    const float km  = 1.0f / tau_mem[0];
    const float kss = 1.0f / tau_syn[0];
    const float vth = v_thresh[0];
    const float vre = v_reset[0];
    const int   T   = tsteps[0];
    const float invT = 1.0f / (float)T;

#pragma unroll
    for (int mt = 0; mt < 2; mt++) {
#pragma unroll
        for (int rs = 0; rs < 2; rs++) {
            const int gm = m0 + wm * 32 + mt * 16 + g + rs * 8;
            float cur[8], vv[8], ii[8], cnt[8];
#pragma unroll
            for (int nt = 0; nt < 4; nt++) {
                const int gc = n0 + wn * 32 + nt * 8 + 2 * tq;
                const size_t off = (size_t)gm * HDIM + gc;
                const float2 v2 = *reinterpret_cast<const float2*>(v0 + off);
                const float2 i2 = *reinterpret_cast<const float2*>(i0 + off);
                cur[2 * nt]     = (mster[mt][nt][rs * 2 + 0] + __ldg(b1 + gc))     * invT;
                cur[2 * nt + 1] = (mster[mt][nt][rs * 2 + 1] + __ldg(b1 + gc + 1)) * invT;
                vv[2 * nt] = v2.x; vv[2 * nt + 1] = v2.y;
                ii[2 * nt] = i2.x; ii[2 * nt + 1] = i2.y;
                cnt[2 * nt] = 0.0f; cnt[2 * nt + 1] = 0.0f;
            }
            for (int t = 0; t < T; t++) {
#pragma unroll
                for (int j = 0; j < 8; j++) {
                    ii[j] = ii[j] - kss * ii[j] + cur[j];
                    vv[j] = vv[j] - km  * vv[j] + ii[j];
                    if (vv[j] >= vth) { cnt[j] += 1.0f; vv[j] = vre; }
                }
            }
#pragma unroll
            for (int nt = 0; nt < 4; nt++) {
                const int gc = n0 + wn * 32 + nt * 8 + 2 * tq;
                float2 s2; s2.x = cnt[2 * nt]; s2.y = cnt[2 * nt + 1];
                *reinterpret_cast<float2*>(spikes + (size_t)gm * HDIM + gc) = s2;
                __nv_bfloat162 sb;
                sb.x = __float2bfloat16(cnt[2 * nt]);
                sb.y = __float2bfloat16(cnt[2 * nt + 1]);
                *reinterpret_cast<__nv_bfloat162*>(g_Sh + (size_t)gm * HDIM + gc) = sb;
            }
        }
    }
}

// ------------------------------ GEMM2 --------------------------------------
// out = [s|s] @ [w1|w2]^T + b2. CTA 128x64, BK=32, 3 stages, 128 chunks.
// Tensor-chain bias ~6e-5 on the output: within tolerance, no drains needed.
#define G2_CHUNKS 128
#define BST2 5120   // 64 rows * 80B per stage

__device__ __forceinline__ void g2_load(uint32_t sA, uint32_t sB, int m0, int n0,
                                        int kt, int st, int tid)
{
    if (tid < 128) {
        const __nv_bfloat16* g = g_Sh + (size_t)(m0 + tid) * HDIM + (kt & 63) * 32;
        const uint32_t d = sA + st * AST + tid * 80;
        CP16(d, g); CP16(d + 16, g + 8); CP16(d + 32, g + 16); CP16(d + 48, g + 24);
    } else if (tid < 192) {
        const int r = tid - 128;
        const __nv_bfloat16* g = g_W2h + (size_t)(n0 + r) * 4096 + kt * 32;
        const uint32_t d = sB + st * BST2 + r * 80;
        CP16(d, g); CP16(d + 16, g + 8); CP16(d + 32, g + 16); CP16(d + 48, g + 24);
    }
}

__global__ __launch_bounds__(256)
void gemm2_kernel(const float* __restrict__ b2, float* __restrict__ out)
{
    extern __shared__ __align__(128) char smem2[];
    const uint32_t sA = smem_u32(smem2);
    const uint32_t sB = sA + 3 * AST;

    const int tid = threadIdx.x, lane = tid & 31, wid = tid >> 5;
    const int wm = wid & 3, wn = wid >> 2;             // warp tile 32x32
    const int g = lane >> 2, tq = lane & 3;
    const int mi = lane >> 3, r8 = lane & 7;
    const int m0 = blockIdx.y * 128, n0 = blockIdx.x * 64;

    const uint32_t aoff = (uint32_t)(((mi & 1) * 8 + r8) * 80 + (mi >> 1) * 16);
    const uint32_t boff = (uint32_t)(((mi >> 1) * 8 + r8) * 80 + (mi & 1) * 16);

    float acc[2][4][4];
#pragma unroll
    for (int a = 0; a < 2; a++)
#pragma unroll
        for (int b = 0; b < 4; b++)
#pragma unroll
            for (int c = 0; c < 4; c++) acc[a][b][c] = 0.0f;

    g2_load(sA, sB, m0, n0, 0, 0, tid); CP_COMMIT();
    g2_load(sA, sB, m0, n0, 1, 1, tid); CP_COMMIT();

    for (int kt = 0; kt < G2_CHUNKS; kt++) {
        const int buf = kt % 3;
        CP_WAIT1();
        __syncthreads();
        if (kt + 2 < G2_CHUNKS) g2_load(sA, sB, m0, n0, kt + 2, (kt + 2) % 3, tid);
        CP_COMMIT();

        const uint32_t Ab = sA + buf * AST + (wm * 32) * 80 + aoff;
        const uint32_t Bb = sB + buf * BST2 + (wn * 32) * 80 + boff;
#pragma unroll
        for (int ks = 0; ks < 2; ks++) {
            uint32_t af[2][4], bfr[2][4];
#pragma unroll
            for (int mt = 0; mt < 2; mt++) LDSM4(af[mt], Ab + mt * 16 * 80 + ks * 32);
#pragma unroll
            for (int np = 0; np < 2; np++) LDSM4(bfr[np], Bb + np * 16 * 80 + ks * 32);
#pragma unroll
            for (int mt = 0; mt < 2; mt++)
#pragma unroll
                for (int nt = 0; nt < 4; nt++)
                    mma_bf16(acc[mt][nt], af[mt], &bfr[nt >> 1][(nt & 1) * 2]);
        }
    }

#pragma unroll
    for (int mt = 0; mt < 2; mt++) {
#pragma unroll
        for (int rs = 0; rs < 2; rs++) {
            const int gm = m0 + wm * 32 + mt * 16 + g + rs * 8;
#pragma unroll
            for (int nt = 0; nt < 4; nt++) {
                const int gc = n0 + wn * 32 + nt * 8 + 2 * tq;
                float2 o2;
                o2.x = acc[mt][nt][rs * 2 + 0] + __ldg(b2 + gc);
                o2.y = acc[mt][nt][rs * 2 + 1] + __ldg(b2 + gc + 1);
                *reinterpret_cast<float2*>(out + (size_t)gm * ODIM + gc) = o2;
            }
        }
    }
}

// ---------------------------------------------------------------------------
extern "C" void kernel_launch(void* const* d_in, const int* in_sizes, int n_in,
                              void* d_out, int out_size)
{
    const float* x        = (const float*)d_in[0];
    const float* W1       = (const float*)d_in[1];
    const float* b1       = (const float*)d_in[2];
    const float* W2       = (const float*)d_in[3];
    const float* b2       = (const float*)d_in[4];
    const float* tau_mem  = (const float*)d_in[5];
    const float* tau_syn  = (const float*)d_in[6];
    const float* v_thresh = (const float*)d_in[7];
    const float* v_reset  = (const float*)d_in[8];
    const float* v0       = (const float*)d_in[9];
    const float* i0       = (const float*)d_in[10];
    const int*   tsteps   = (const int*)d_in[11];

    float* out    = (float*)d_out;
    float* spikes = out + (size_t)BDIM * ODIM;

    __nv_bfloat16 *dA1, *dB1, *dW2;
    cudaGetSymbolAddress((void**)&dA1, g_A1h);
    cudaGetSymbolAddress((void**)&dB1, g_B1h);
    cudaGetSymbolAddress((void**)&dW2, g_W2h);

    const int smem1 = 6 * AST;               // 61440
    const int smem2 = 3 * AST + 3 * BST2;    // 46080
    cudaFuncSetAttribute(gemm1_lif_kernel, cudaFuncAttributeMaxDynamicSharedMemorySize, smem1);
    cudaFuncSetAttribute(gemm2_kernel,     cudaFuncAttributeMaxDynamicSharedMemorySize, smem2);

    split3_kernel<<<2048, 256>>>(x,  dA1, BDIM * INDIM);
    split3_kernel<<<1024, 256>>>(W1, dB1, HDIM * INDIM);
    split2_kernel<<<256,  256>>>(W2, dW2, ODIM * HDIM);

    dim3 g1(HDIM / 128, BDIM / 128);   // 16 x 32 = 512 CTAs
    gemm1_lif_kernel<<<g1, 512, smem1>>>(b1, v0, i0, tau_mem, tau_syn,
                                         v_thresh, v_reset, tsteps, spikes);

    dim3 g2(ODIM / 64, BDIM / 128);    // 4 x 32 = 128 CTAs
    gemm2_kernel<<<g2, 256, smem2>>>(b2, out);
}

// round 11
// speedup vs baseline: 1.2664x; 1.0854x over previous
#include <cuda_runtime.h>
#include <cuda_bf16.h>
#include <cstdint>

// ---------------------------------------------------------------------------
// SimpleSNN via bf16x6 emulated-fp32 GEMMs on mma.sync (sm_80+ family ISA).
// Numerics (R8/R9, passing): 6 products; corrections (2^-9 scale) in one
// tensor chain; dominant a1b1 drained into RN fp32 masters per chunk.
// R10: gemm1 BK=64, 4-stage cp.async, wait_group 2 (prefetch distance ~2.5
// chunks); 96 chunks, half the barriers. gemm2 deepened to 4 stages.
// d_out layout: [ output (B*OUT) | total_spikes (B*H) ]
// ---------------------------------------------------------------------------

#define BDIM 4096
#define INDIM 1024
#define HDIM 2048
#define ODIM 256

__device__ __nv_bfloat16 g_A1h[(size_t)BDIM * 3072];  // x   [a1|a2|a3]
__device__ __nv_bfloat16 g_B1h[(size_t)HDIM * 3072];  // W1  [b1|b2|b3]
__device__ __nv_bfloat16 g_Sh [(size_t)BDIM * HDIM];  // spikes bf16 (exact)
__device__ __nv_bfloat16 g_W2h[(size_t)ODIM * 4096];  // W2  [w1|w2]

// ------------------------------ helpers ------------------------------------
__device__ __forceinline__ uint32_t smem_u32(const void* p) {
    uint32_t a;
    asm("{ .reg .u64 t; cvta.to.shared.u64 t, %1; cvt.u32.u64 %0, t; }" : "=r"(a) : "l"(p));
    return a;
}
#define CP16(dst, src)  asm volatile("cp.async.cg.shared.global [%0], [%1], 16;" :: "r"(dst), "l"(src))
#define CP_COMMIT()     asm volatile("cp.async.commit_group;" ::: "memory")
#define CP_WAIT2()      asm volatile("cp.async.wait_group 2;" ::: "memory")
#define LDSM4(R, a) asm volatile("ldmatrix.sync.aligned.m8n8.x4.shared.b16 {%0,%1,%2,%3}, [%4];" \
    : "=r"((R)[0]), "=r"((R)[1]), "=r"((R)[2]), "=r"((R)[3]) : "r"(a))

__device__ __forceinline__ void mma_bf16(float* c, const uint32_t* a, const uint32_t* b) {
    asm volatile(
        "mma.sync.aligned.m16n8k16.row.col.f32.bf16.bf16.f32 "
        "{%0,%1,%2,%3}, {%4,%5,%6,%7}, {%8,%9}, {%0,%1,%2,%3};"
        : "+f"(c[0]), "+f"(c[1]), "+f"(c[2]), "+f"(c[3])
        : "r"(a[0]), "r"(a[1]), "r"(a[2]), "r"(a[3]), "r"(b[0]), "r"(b[1]));
}

// ------------------------------ split kernels ------------------------------
__global__ void split3_kernel(const float* __restrict__ src, __nv_bfloat16* __restrict__ dst,
                              int total)  // K=1024, dst stride 3072
{
    for (int e = blockIdx.x * blockDim.x + threadIdx.x; e < total; e += gridDim.x * blockDim.x) {
        const int r = e >> 10, k = e & 1023;
        const float a = src[e];
        const __nv_bfloat16 a1 = __float2bfloat16(a);
        const float r1 = a - __bfloat162float(a1);     // exact
        const __nv_bfloat16 a2 = __float2bfloat16(r1);
        const float r2 = r1 - __bfloat162float(a2);    // exact
        const __nv_bfloat16 a3 = __float2bfloat16(r2);
        __nv_bfloat16* d = dst + (size_t)r * 3072;
        d[k] = a1; d[1024 + k] = a2; d[2048 + k] = a3;
    }
}
__global__ void split2_kernel(const float* __restrict__ src, __nv_bfloat16* __restrict__ dst,
                              int total)  // K=2048, dst stride 4096
{
    for (int e = blockIdx.x * blockDim.x + threadIdx.x; e < total; e += gridDim.x * blockDim.x) {
        const int r = e >> 11, k = e & 2047;
        const float a = src[e];
        const __nv_bfloat16 a1 = __float2bfloat16(a);
        const __nv_bfloat16 a2 = __float2bfloat16(a - __bfloat162float(a1));
        __nv_bfloat16* d = dst + (size_t)r * 4096;
        d[k] = a1; d[2048 + k] = a2;
    }
}

// ------------------------------ GEMM1 + LIF --------------------------------
// CTA 128x128, 512 threads, warp grid 4(m)x4(n), warp tile 32x32.
// BK=64 bf16 (128B rows padded to 144B), 4-stage cp.async, wait_group 2.
// 96 chunks = 6 products x 16. Product order: A {a1,a2,a1,a2,a3,a1},
// B {b2,b1,b3,b2,b1,b1}; corrections chunks 0-79, a1b1 chunks 80-95.
#define G1_CHUNKS 96
#define RB1 144              // bytes per smem row
#define AST1 (128 * RB1)     // 18432 B per stage per matrix

__device__ __forceinline__ void g1_load(uint32_t sA, uint32_t sB, int m0, int n0,
                                        int kt, int st, int tid)
{
    const int p = kt >> 4, cc = kt & 15;
    const int row = (tid >> 1) & 127, part = tid & 1;   // part: 64B half of 128B row
    if (tid < 256) {
        const int sec = (0x021010 >> (p * 4)) & 0xF;            // a: 0,1,0,1,2,0
        const __nv_bfloat16* g = g_A1h + (size_t)(m0 + row) * 3072 + sec * 1024 + cc * 64 + part * 32;
        const uint32_t d = sA + st * AST1 + row * RB1 + part * 64;
        CP16(d, g); CP16(d + 16, g + 8); CP16(d + 32, g + 16); CP16(d + 48, g + 24);
    } else {
        const int sec = (0x001201 >> (p * 4)) & 0xF;            // b: 1,0,2,1,0,0
        const __nv_bfloat16* g = g_B1h + (size_t)(n0 + row) * 3072 + sec * 1024 + cc * 64 + part * 32;
        const uint32_t d = sB + st * AST1 + row * RB1 + part * 64;
        CP16(d, g); CP16(d + 16, g + 8); CP16(d + 32, g + 16); CP16(d + 48, g + 24);
    }
}

__global__ __launch_bounds__(512)
void gemm1_lif_kernel(const float* __restrict__ b1, const float* __restrict__ v0,
                      const float* __restrict__ i0, const float* __restrict__ tau_mem,
                      const float* __restrict__ tau_syn, const float* __restrict__ v_thresh,
                      const float* __restrict__ v_reset, const int* __restrict__ tsteps,
                      float* __restrict__ spikes)
{
    extern __shared__ __align__(128) char smem[];
    const uint32_t sA = smem_u32(smem);
    const uint32_t sB = sA + 4 * AST1;

    const int tid = threadIdx.x, lane = tid & 31, wid = tid >> 5;
    const int wm = wid & 3, wn = wid >> 2;             // warp tile 32x32
    const int g = lane >> 2, tq = lane & 3;
    const int mi = lane >> 3, r8 = lane & 7;
    const int m0 = blockIdx.y * 128, n0 = blockIdx.x * 128;

    const uint32_t aoff = (uint32_t)(((mi & 1) * 8 + r8) * RB1 + (mi >> 1) * 16);
    const uint32_t boff = (uint32_t)(((mi >> 1) * 8 + r8) * RB1 + (mi & 1) * 16);

    float mster[2][4][4];   // RN fp32 master accumulators
    float tacc[2][4][4];    // tensor-core temp accumulators
#pragma unroll
    for (int a = 0; a < 2; a++)
#pragma unroll
        for (int b = 0; b < 4; b++)
#pragma unroll
            for (int c = 0; c < 4; c++) { mster[a][b][c] = 0.0f; tacc[a][b][c] = 0.0f; }

    g1_load(sA, sB, m0, n0, 0, 0, tid); CP_COMMIT();
    g1_load(sA, sB, m0, n0, 1, 1, tid); CP_COMMIT();
    g1_load(sA, sB, m0, n0, 2, 2, tid); CP_COMMIT();

    for (int kt = 0; kt < G1_CHUNKS; kt++) {
        const int buf = kt & 3;
        CP_WAIT2();
        __syncthreads();
        if (kt + 3 < G1_CHUNKS) g1_load(sA, sB, m0, n0, kt + 3, (kt + 3) & 3, tid);
        CP_COMMIT();

        const uint32_t Ab = sA + buf * AST1 + (wm * 32) * RB1 + aoff;
        const uint32_t Bb = sB + buf * AST1 + (wn * 32) * RB1 + boff;
#pragma unroll
        for (int ks = 0; ks < 4; ks++) {
            uint32_t af[2][4], bfr[2][4];
#pragma unroll
            for (int mt = 0; mt < 2; mt++) LDSM4(af[mt], Ab + mt * 16 * RB1 + ks * 32);
#pragma unroll
            for (int np = 0; np < 2; np++) LDSM4(bfr[np], Bb + np * 16 * RB1 + ks * 32);
#pragma unroll
            for (int mt = 0; mt < 2; mt++)
#pragma unroll
                for (int nt = 0; nt < 4; nt++)
                    mma_bf16(tacc[mt][nt], af[mt], &bfr[nt >> 1][(nt & 1) * 2]);
        }
        // Drain: once after all corrections (kt==79), then every a1b1 chunk.
        if (kt >= 79) {
#pragma unroll
            for (int a = 0; a < 2; a++)
#pragma unroll
                for (int b = 0; b < 4; b++)
#pragma unroll
                    for (int c = 0; c < 4; c++) {
                        mster[a][b][c] += tacc[a][b][c];
                        tacc[a][b][c] = 0.0f;
                    }
        }
    }
    // C frag: c0=(g,2tq) c1=(g,2tq+1) c2=(g+8,2tq) c3=(g+8,2tq+1)

    // -------------------- fused LIF epilogue --------------------
    const float km  = 1.0f / tau_mem[0];
    const float kss = 1.0f / tau_syn[0];
    const float vth = v_thresh[0];
    const float vre = v_reset[0];
    const int   T   = tsteps[0];
    const float invT = 1.0f / (float)T;

#pragma unroll
    for (int mt = 0; mt < 2; mt++) {
#pragma unroll
        for (int rs = 0; rs < 2; rs++) {
            const int gm = m0 + wm * 32 + mt * 16 + g + rs * 8;
            float cur[8], vv[8], ii[8], cnt[8];
#pragma unroll
            for (int nt = 0; nt < 4; nt++) {
                const int gc = n0 + wn * 32 + nt * 8 + 2 * tq;
                const size_t off = (size_t)gm * HDIM + gc;
                const float2 v2 = *reinterpret_cast<const float2*>(v0 + off);
                const float2 i2 = *reinterpret_cast<const float2*>(i0 + off);
                cur[2 * nt]     = (mster[mt][nt][rs * 2 + 0] + __ldg(b1 + gc))     * invT;
                cur[2 * nt + 1] = (mster[mt][nt][rs * 2 + 1] + __ldg(b1 + gc + 1)) * invT;
                vv[2 * nt] = v2.x; vv[2 * nt + 1] = v2.y;
                ii[2 * nt] = i2.x; ii[2 * nt + 1] = i2.y;
                cnt[2 * nt] = 0.0f; cnt[2 * nt + 1] = 0.0f;
            }
            for (int t = 0; t < T; t++) {
#pragma unroll
                for (int j = 0; j < 8; j++) {
                    ii[j] = ii[j] - kss * ii[j] + cur[j];
                    vv[j] = vv[j] - km  * vv[j] + ii[j];
                    if (vv[j] >= vth) { cnt[j] += 1.0f; vv[j] = vre; }
                }
            }
#pragma unroll
            for (int nt = 0; nt < 4; nt++) {
                const int gc = n0 + wn * 32 + nt * 8 + 2 * tq;
                float2 s2; s2.x = cnt[2 * nt]; s2.y = cnt[2 * nt + 1];
                *reinterpret_cast<float2*>(spikes + (size_t)gm * HDIM + gc) = s2;
                __nv_bfloat162 sb;
                sb.x = __float2bfloat16(cnt[2 * nt]);
                sb.y = __float2bfloat16(cnt[2 * nt + 1]);
                *reinterpret_cast<__nv_bfloat162*>(g_Sh + (size_t)gm * HDIM + gc) = sb;
            }
        }
    }
}

// ------------------------------ GEMM2 --------------------------------------
// out = [s|s] @ [w1|w2]^T + b2. CTA 128x64, BK=32, 4 stages, wait_group 2,
// 128 chunks. Tensor-chain bias ~6e-5 on output: within tolerance, no drains.
#define G2_CHUNKS 128
#define AST2 10240   // 128 rows * 80B per stage
#define BST2 5120    // 64 rows * 80B per stage

__device__ __forceinline__ void g2_load(uint32_t sA, uint32_t sB, int m0, int n0,
                                        int kt, int st, int tid)
{
    if (tid < 128) {
        const __nv_bfloat16* g = g_Sh + (size_t)(m0 + tid) * HDIM + (kt & 63) * 32;
        const uint32_t d = sA + st * AST2 + tid * 80;
        CP16(d, g); CP16(d + 16, g + 8); CP16(d + 32, g + 16); CP16(d + 48, g + 24);
    } else if (tid < 192) {
        const int r = tid - 128;
        const __nv_bfloat16* g = g_W2h + (size_t)(n0 + r) * 4096 + kt * 32;
        const uint32_t d = sB + st * BST2 + r * 80;
        CP16(d, g); CP16(d + 16, g + 8); CP16(d + 32, g + 16); CP16(d + 48, g + 24);
    }
}

__global__ __launch_bounds__(256)
void gemm2_kernel(const float* __restrict__ b2, float* __restrict__ out)
{
    extern __shared__ __align__(128) char smem2[];
    const uint32_t sA = smem_u32(smem2);
    const uint32_t sB = sA + 4 * AST2;

    const int tid = threadIdx.x, lane = tid & 31, wid = tid >> 5;
    const int wm = wid & 3, wn = wid >> 2;             // warp tile 32x32
    const int g = lane >> 2, tq = lane & 3;
    const int mi = lane >> 3, r8 = lane & 7;
    const int m0 = blockIdx.y * 128, n0 = blockIdx.x * 64;

    const uint32_t aoff = (uint32_t)(((mi & 1) * 8 + r8) * 80 + (mi >> 1) * 16);
    const uint32_t boff = (uint32_t)(((mi >> 1) * 8 + r8) * 80 + (mi & 1) * 16);

    float acc[2][4][4];
#pragma unroll
    for (int a = 0; a < 2; a++)
#pragma unroll
        for (int b = 0; b < 4; b++)
#pragma unroll
            for (int c = 0; c < 4; c++) acc[a][b][c] = 0.0f;

    g2_load(sA, sB, m0, n0, 0, 0, tid); CP_COMMIT();
    g2_load(sA, sB, m0, n0, 1, 1, tid); CP_COMMIT();
    g2_load(sA, sB, m0, n0, 2, 2, tid); CP_COMMIT();

    for (int kt = 0; kt < G2_CHUNKS; kt++) {
        const int buf = kt & 3;
        CP_WAIT2();
        __syncthreads();
        if (kt + 3 < G2_CHUNKS) g2_load(sA, sB, m0, n0, kt + 3, (kt + 3) & 3, tid);
        CP_COMMIT();

        const uint32_t Ab = sA + buf * AST2 + (wm * 32) * 80 + aoff;
        const uint32_t Bb = sB + buf * BST2 + (wn * 32) * 80 + boff;
#pragma unroll
        for (int ks = 0; ks < 2; ks++) {
            uint32_t af[2][4], bfr[2][4];
#pragma unroll
            for (int mt = 0; mt < 2; mt++) LDSM4(af[mt], Ab + mt * 16 * 80 + ks * 32);
#pragma unroll
            for (int np = 0; np < 2; np++) LDSM4(bfr[np], Bb + np * 16 * 80 + ks * 32);
#pragma unroll
            for (int mt = 0; mt < 2; mt++)
#pragma unroll
                for (int nt = 0; nt < 4; nt++)
                    mma_bf16(acc[mt][nt], af[mt], &bfr[nt >> 1][(nt & 1) * 2]);
        }
    }

#pragma unroll
    for (int mt = 0; mt < 2; mt++) {
#pragma unroll
        for (int rs = 0; rs < 2; rs++) {
            const int gm = m0 + wm * 32 + mt * 16 + g + rs * 8;
#pragma unroll
            for (int nt = 0; nt < 4; nt++) {
                const int gc = n0 + wn * 32 + nt * 8 + 2 * tq;
                float2 o2;
                o2.x = acc[mt][nt][rs * 2 + 0] + __ldg(b2 + gc);
                o2.y = acc[mt][nt][rs * 2 + 1] + __ldg(b2 + gc + 1);
                *reinterpret_cast<float2*>(out + (size_t)gm * ODIM + gc) = o2;
            }
        }
    }
}

// ---------------------------------------------------------------------------
extern "C" void kernel_launch(void* const* d_in, const int* in_sizes, int n_in,
                              void* d_out, int out_size)
{
    const float* x        = (const float*)d_in[0];
    const float* W1       = (const float*)d_in[1];
    const float* b1       = (const float*)d_in[2];
    const float* W2       = (const float*)d_in[3];
    const float* b2       = (const float*)d_in[4];
    const float* tau_mem  = (const float*)d_in[5];
    const float* tau_syn  = (const float*)d_in[6];
    const float* v_thresh = (const float*)d_in[7];
    const float* v_reset  = (const float*)d_in[8];
    const float* v0       = (const float*)d_in[9];
    const float* i0       = (const float*)d_in[10];
    const int*   tsteps   = (const int*)d_in[11];

    float* out    = (float*)d_out;
    float* spikes = out + (size_t)BDIM * ODIM;

    __nv_bfloat16 *dA1, *dB1, *dW2;
    cudaGetSymbolAddress((void**)&dA1, g_A1h);
    cudaGetSymbolAddress((void**)&dB1, g_B1h);
    cudaGetSymbolAddress((void**)&dW2, g_W2h);

    const int smem1 = 8 * AST1;              // 147456
    const int smem2 = 4 * (AST2 + BST2);     // 61440
    cudaFuncSetAttribute(gemm1_lif_kernel, cudaFuncAttributeMaxDynamicSharedMemorySize, smem1);
    cudaFuncSetAttribute(gemm2_kernel,     cudaFuncAttributeMaxDynamicSharedMemorySize, smem2);

    split3_kernel<<<2048, 256>>>(x,  dA1, BDIM * INDIM);
    split3_kernel<<<1024, 256>>>(W1, dB1, HDIM * INDIM);
    split2_kernel<<<256,  256>>>(W2, dW2, ODIM * HDIM);

    dim3 g1(HDIM / 128, BDIM / 128);   // 16 x 32 = 512 CTAs
    gemm1_lif_kernel<<<g1, 512, smem1>>>(b1, v0, i0, tau_mem, tau_syn,
                                         v_thresh, v_reset, tsteps, spikes);

    dim3 g2(ODIM / 64, BDIM / 128);    // 4 x 32 = 128 CTAs
    gemm2_kernel<<<g2, 256, smem2>>>(b2, out);
}

// round 13
// speedup vs baseline: 2.0380x; 1.6094x over previous
#include <cuda_runtime.h>
#include <cuda_bf16.h>
#include <cuda_fp16.h>
#include <cstdint>

// ---------------------------------------------------------------------------
// SimpleSNN, emulated-fp32 GEMMs on mma.sync (sm_80+ family ISA).
// GEMM1 (R12): fp16 2-split x = a1 + 2^-12*a2', W1 = b1 + 2^-12*b2'
//   (low parts pre-scaled by 2^12 to stay in fp16 normal range).
//   3 products: corrections a1*b2' + a2'*b1 (one tensor chain, drained once
//   with x2^-12), then dominant a1*b1 (drained into RN fp32 masters per
//   chunk to defeat the truncating tensor accumulator — R8 finding).
//   51.5 GF of HMMA vs 103 GF for the bf16x6 scheme: half the legacy wall.
// GEMM2: unchanged bf16 path (spikes exact bf16 @ [w1|w2] 2-split).
// d_out layout: [ output (B*OUT) | total_spikes (B*H) ]
// ---------------------------------------------------------------------------

#define BDIM 4096
#define INDIM 1024
#define HDIM 2048
#define ODIM 256

__device__ __half         g_A1H[(size_t)BDIM * 2048];  // x   [a1|a2'*2^12]
__device__ __half         g_B1H[(size_t)HDIM * 2048];  // W1  [b1|b2'*2^12]
__device__ __nv_bfloat16  g_Sh [(size_t)BDIM * HDIM];  // spikes bf16 (exact)
__device__ __nv_bfloat16  g_W2h[(size_t)ODIM * 4096];  // W2  [w1|w2]

// ------------------------------ helpers ------------------------------------
__device__ __forceinline__ uint32_t smem_u32(const void* p) {
    uint32_t a;
    asm("{ .reg .u64 t; cvta.to.shared.u64 t, %1; cvt.u32.u64 %0, t; }" : "=r"(a) : "l"(p));
    return a;
}
#define CP16(dst, src)  asm volatile("cp.async.cg.shared.global [%0], [%1], 16;" :: "r"(dst), "l"(src))
#define CP_COMMIT()     asm volatile("cp.async.commit_group;" ::: "memory")
#define CP_WAIT2()      asm volatile("cp.async.wait_group 2;" ::: "memory")
#define LDSM4(R, a) asm volatile("ldmatrix.sync.aligned.m8n8.x4.shared.b16 {%0,%1,%2,%3}, [%4];" \
    : "=r"((R)[0]), "=r"((R)[1]), "=r"((R)[2]), "=r"((R)[3]) : "r"(a))

__device__ __forceinline__ void mma_f16(float* c, const uint32_t* a, const uint32_t* b) {
    asm volatile(
        "mma.sync.aligned.m16n8k16.row.col.f32.f16.f16.f32 "
        "{%0,%1,%2,%3}, {%4,%5,%6,%7}, {%8,%9}, {%0,%1,%2,%3};"
        : "+f"(c[0]), "+f"(c[1]), "+f"(c[2]), "+f"(c[3])
        : "r"(a[0]), "r"(a[1]), "r"(a[2]), "r"(a[3]), "r"(b[0]), "r"(b[1]));
}
__device__ __forceinline__ void mma_bf16(float* c, const uint32_t* a, const uint32_t* b) {
    asm volatile(
        "mma.sync.aligned.m16n8k16.row.col.f32.bf16.bf16.f32 "
        "{%0,%1,%2,%3}, {%4,%5,%6,%7}, {%8,%9}, {%0,%1,%2,%3};"
        : "+f"(c[0]), "+f"(c[1]), "+f"(c[2]), "+f"(c[3])
        : "r"(a[0]), "r"(a[1]), "r"(a[2]), "r"(a[3]), "r"(b[0]), "r"(b[1]));
}

// ------------------------------ split kernels ------------------------------
// fp16 2-split with scaled low part: a = h1 + 2^-12 * h2', h2' in normal range.
// r = a - (float)h1 is exact (Sterbenz); r*4096 exact (power of 2).
__global__ void splitf16_kernel(const float* __restrict__ src, __half* __restrict__ dst,
                                int total)  // K=1024, dst stride 2048
{
    for (int e = blockIdx.x * blockDim.x + threadIdx.x; e < total; e += gridDim.x * blockDim.x) {
        const int r = e >> 10, k = e & 1023;
        const float a = src[e];
        const __half h1 = __float2half_rn(a);
        const float rr = a - __half2float(h1);
        const __half h2 = __float2half_rn(rr * 4096.0f);
        __half* d = dst + (size_t)r * 2048;
        d[k] = h1; d[1024 + k] = h2;
    }
}
__global__ void split2_kernel(const float* __restrict__ src, __nv_bfloat16* __restrict__ dst,
                              int total)  // K=2048, dst stride 4096 (W2, bf16)
{
    for (int e = blockIdx.x * blockDim.x + threadIdx.x; e < total; e += gridDim.x * blockDim.x) {
        const int r = e >> 11, k = e & 2047;
        const float a = src[e];
        const __nv_bfloat16 a1 = __float2bfloat16(a);
        const __nv_bfloat16 a2 = __float2bfloat16(a - __bfloat162float(a1));
        __nv_bfloat16* d = dst + (size_t)r * 4096;
        d[k] = a1; d[2048 + k] = a2;
    }
}

// ------------------------------ GEMM1 + LIF --------------------------------
// CTA 128x128, 512 threads, warp grid 4(m)x4(n), warp tile 32x32.
// BK=64 fp16 (128B rows padded to 144B), 4-stage cp.async, wait_group 2.
// 48 chunks = 3 products x 16:
//   p0 (0-15):  a1  x b2'   } corrections, one chain, drained x2^-12 at kt=31
//   p1 (16-31): a2' x b1    }
//   p2 (32-47): a1  x b1    — drained into masters every chunk
#define G1_CHUNKS 48
#define RB1 144              // bytes per smem row
#define AST1 (128 * RB1)     // 18432 B per stage per matrix

__device__ __forceinline__ void g1_load(uint32_t sA, uint32_t sB, int m0, int n0,
                                        int kt, int st, int tid)
{
    const int p = kt >> 4, cc = kt & 15;
    const int row = (tid >> 1) & 127, part = tid & 1;   // part: 64B half of 128B row
    if (tid < 256) {
        const int sec = (p == 1) ? 1 : 0;               // a: a1, a2', a1
        const __half* g = g_A1H + (size_t)(m0 + row) * 2048 + sec * 1024 + cc * 64 + part * 32;
        const uint32_t d = sA + st * AST1 + row * RB1 + part * 64;
        CP16(d, g); CP16(d + 16, g + 8); CP16(d + 32, g + 16); CP16(d + 48, g + 24);
    } else {
        const int sec = (p == 0) ? 1 : 0;               // b: b2', b1, b1
        const __half* g = g_B1H + (size_t)(n0 + row) * 2048 + sec * 1024 + cc * 64 + part * 32;
        const uint32_t d = sB + st * AST1 + row * RB1 + part * 64;
        CP16(d, g); CP16(d + 16, g + 8); CP16(d + 32, g + 16); CP16(d + 48, g + 24);
    }
}

__global__ __launch_bounds__(512)
void gemm1_lif_kernel(const float* __restrict__ b1, const float* __restrict__ v0,
                      const float* __restrict__ i0, const float* __restrict__ tau_mem,
                      const float* __restrict__ tau_syn, const float* __restrict__ v_thresh,
                      const float* __restrict__ v_reset, const int* __restrict__ tsteps,
                      float* __restrict__ spikes)
{
    extern __shared__ __align__(128) char smem[];
    const uint32_t sA = smem_u32(smem);
    const uint32_t sB = sA + 4 * AST1;

    const int tid = threadIdx.x, lane = tid & 31, wid = tid >> 5;
    const int wm = wid & 3, wn = wid >> 2;             // warp tile 32x32
    const int g = lane >> 2, tq = lane & 3;
    const int mi = lane >> 3, r8 = lane & 7;
    const int m0 = blockIdx.y * 128, n0 = blockIdx.x * 128;

    const uint32_t aoff = (uint32_t)(((mi & 1) * 8 + r8) * RB1 + (mi >> 1) * 16);
    const uint32_t boff = (uint32_t)(((mi >> 1) * 8 + r8) * RB1 + (mi & 1) * 16);

    float mster[2][4][4];   // RN fp32 master accumulators
    float tacc[2][4][4];    // tensor-core temp accumulators
#pragma unroll
    for (int a = 0; a < 2; a++)
#pragma unroll
        for (int b = 0; b < 4; b++)
#pragma unroll
            for (int c = 0; c < 4; c++) { mster[a][b][c] = 0.0f; tacc[a][b][c] = 0.0f; }

    g1_load(sA, sB, m0, n0, 0, 0, tid); CP_COMMIT();
    g1_load(sA, sB, m0, n0, 1, 1, tid); CP_COMMIT();
    g1_load(sA, sB, m0, n0, 2, 2, tid); CP_COMMIT();

    for (int kt = 0; kt < G1_CHUNKS; kt++) {
        const int buf = kt & 3;
        CP_WAIT2();
        __syncthreads();
        if (kt + 3 < G1_CHUNKS) g1_load(sA, sB, m0, n0, kt + 3, (kt + 3) & 3, tid);
        CP_COMMIT();

        const uint32_t Ab = sA + buf * AST1 + (wm * 32) * RB1 + aoff;
        const uint32_t Bb = sB + buf * AST1 + (wn * 32) * RB1 + boff;
#pragma unroll
        for (int ks = 0; ks < 4; ks++) {
            uint32_t af[2][4], bfr[2][4];
#pragma unroll
            for (int mt = 0; mt < 2; mt++) LDSM4(af[mt], Ab + mt * 16 * RB1 + ks * 32);
#pragma unroll
            for (int np = 0; np < 2; np++) LDSM4(bfr[np], Bb + np * 16 * RB1 + ks * 32);
#pragma unroll
            for (int mt = 0; mt < 2; mt++)
#pragma unroll
                for (int nt = 0; nt < 4; nt++)
                    mma_f16(tacc[mt][nt], af[mt], &bfr[nt >> 1][(nt & 1) * 2]);
        }
        // Drain: corrections once at kt==31 (undo the 2^12 scale), then every
        // a1b1 chunk to defeat the truncating tensor accumulator.
        if (kt >= 31) {
            const float sc = (kt == 31) ? (1.0f / 4096.0f) : 1.0f;
#pragma unroll
            for (int a = 0; a < 2; a++)
#pragma unroll
                for (int b = 0; b < 4; b++)
#pragma unroll
                    for (int c = 0; c < 4; c++) {
                        mster[a][b][c] += tacc[a][b][c] * sc;
                        tacc[a][b][c] = 0.0f;
                    }
        }
    }
    // C frag: c0=(g,2tq) c1=(g,2tq+1) c2=(g+8,2tq) c3=(g+8,2tq+1)

    // -------------------- fused LIF epilogue --------------------
    const float km  = 1.0f / tau_mem[0];
    const float kss = 1.0f / tau_syn[0];
    const float vth = v_thresh[0];
    const float vre = v_reset[0];
    const int   T   = tsteps[0];
    const float invT = 1.0f / (float)T;

#pragma unroll
    for (int mt = 0; mt < 2; mt++) {
#pragma unroll
        for (int rs = 0; rs < 2; rs++) {
            const int gm = m0 + wm * 32 + mt * 16 + g + rs * 8;
            float cur[8], vv[8], ii[8], cnt[8];
#pragma unroll
            for (int nt = 0; nt < 4; nt++) {
                const int gc = n0 + wn * 32 + nt * 8 + 2 * tq;
                const size_t off = (size_t)gm * HDIM + gc;
                const float2 v2 = *reinterpret_cast<const float2*>(v0 + off);
                const float2 i2 = *reinterpret_cast<const float2*>(i0 + off);
                cur[2 * nt]     = (mster[mt][nt][rs * 2 + 0] + __ldg(b1 + gc))     * invT;
                cur[2 * nt + 1] = (mster[mt][nt][rs * 2 + 1] + __ldg(b1 + gc + 1)) * invT;
                vv[2 * nt] = v2.x; vv[2 * nt + 1] = v2.y;
                ii[2 * nt] = i2.x; ii[2 * nt + 1] = i2.y;
                cnt[2 * nt] = 0.0f; cnt[2 * nt + 1] = 0.0f;
            }
            for (int t = 0; t < T; t++) {
#pragma unroll
                for (int j = 0; j < 8; j++) {
                    ii[j] = ii[j] - kss * ii[j] + cur[j];
                    vv[j] = vv[j] - km  * vv[j] + ii[j];
                    if (vv[j] >= vth) { cnt[j] += 1.0f; vv[j] = vre; }
                }
            }
#pragma unroll
            for (int nt = 0; nt < 4; nt++) {
                const int gc = n0 + wn * 32 + nt * 8 + 2 * tq;
                float2 s2; s2.x = cnt[2 * nt]; s2.y = cnt[2 * nt + 1];
                *reinterpret_cast<float2*>(spikes + (size_t)gm * HDIM + gc) = s2;
                __nv_bfloat162 sb;
                sb.x = __float2bfloat16(cnt[2 * nt]);
                sb.y = __float2bfloat16(cnt[2 * nt + 1]);
                *reinterpret_cast<__nv_bfloat162*>(g_Sh + (size_t)gm * HDIM + gc) = sb;
            }
        }
    }
}

// ------------------------------ GEMM2 --------------------------------------
// out = [s|s] @ [w1|w2]^T + b2. CTA 128x64, BK=32, 4 stages, wait_group 2,
// 128 chunks. Tensor-chain bias ~6e-5 on output: within tolerance, no drains.
#define G2_CHUNKS 128
#define AST2 10240   // 128 rows * 80B per stage
#define BST2 5120    // 64 rows * 80B per stage

__device__ __forceinline__ void g2_load(uint32_t sA, uint32_t sB, int m0, int n0,
                                        int kt, int st, int tid)
{
    if (tid < 128) {
        const __nv_bfloat16* g = g_Sh + (size_t)(m0 + tid) * HDIM + (kt & 63) * 32;
        const uint32_t d = sA + st * AST2 + tid * 80;
        CP16(d, g); CP16(d + 16, g + 8); CP16(d + 32, g + 16); CP16(d + 48, g + 24);
    } else if (tid < 192) {
        const int r = tid - 128;
        const __nv_bfloat16* g = g_W2h + (size_t)(n0 + r) * 4096 + kt * 32;
        const uint32_t d = sB + st * BST2 + r * 80;
        CP16(d, g); CP16(d + 16, g + 8); CP16(d + 32, g + 16); CP16(d + 48, g + 24);
    }
}

__global__ __launch_bounds__(256)
void gemm2_kernel(const float* __restrict__ b2, float* __restrict__ out)
{
    extern __shared__ __align__(128) char smem2[];
    const uint32_t sA = smem_u32(smem2);
    const uint32_t sB = sA + 4 * AST2;

    const int tid = threadIdx.x, lane = tid & 31, wid = tid >> 5;
    const int wm = wid & 3, wn = wid >> 2;             // warp tile 32x32
    const int g = lane >> 2, tq = lane & 3;
    const int mi = lane >> 3, r8 = lane & 7;
    const int m0 = blockIdx.y * 128, n0 = blockIdx.x * 64;

    const uint32_t aoff = (uint32_t)(((mi & 1) * 8 + r8) * 80 + (mi >> 1) * 16);
    const uint32_t boff = (uint32_t)(((mi >> 1) * 8 + r8) * 80 + (mi & 1) * 16);

    float acc[2][4][4];
#pragma unroll
    for (int a = 0; a < 2; a++)
#pragma unroll
        for (int b = 0; b < 4; b++)
#pragma unroll
            for (int c = 0; c < 4; c++) acc[a][b][c] = 0.0f;

    g2_load(sA, sB, m0, n0, 0, 0, tid); CP_COMMIT();
    g2_load(sA, sB, m0, n0, 1, 1, tid); CP_COMMIT();
    g2_load(sA, sB, m0, n0, 2, 2, tid); CP_COMMIT();

    for (int kt = 0; kt < G2_CHUNKS; kt++) {
        const int buf = kt & 3;
        CP_WAIT2();
        __syncthreads();
        if (kt + 3 < G2_CHUNKS) g2_load(sA, sB, m0, n0, kt + 3, (kt + 3) & 3, tid);
        CP_COMMIT();

        const uint32_t Ab = sA + buf * AST2 + (wm * 32) * 80 + aoff;
        const uint32_t Bb = sB + buf * BST2 + (wn * 32) * 80 + boff;
#pragma unroll
        for (int ks = 0; ks < 2; ks++) {
            uint32_t af[2][4], bfr[2][4];
#pragma unroll
            for (int mt = 0; mt < 2; mt++) LDSM4(af[mt], Ab + mt * 16 * 80 + ks * 32);
#pragma unroll
            for (int np = 0; np < 2; np++) LDSM4(bfr[np], Bb + np * 16 * 80 + ks * 32);
#pragma unroll
            for (int mt = 0; mt < 2; mt++)
#pragma unroll
                for (int nt = 0; nt < 4; nt++)
                    mma_bf16(acc[mt][nt], af[mt], &bfr[nt >> 1][(nt & 1) * 2]);
        }
    }

#pragma unroll
    for (int mt = 0; mt < 2; mt++) {
#pragma unroll
        for (int rs = 0; rs < 2; rs++) {
            const int gm = m0 + wm * 32 + mt * 16 + g + rs * 8;
#pragma unroll
            for (int nt = 0; nt < 4; nt++) {
                const int gc = n0 + wn * 32 + nt * 8 + 2 * tq;
                float2 o2;
                o2.x = acc[mt][nt][rs * 2 + 0] + __ldg(b2 + gc);
                o2.y = acc[mt][nt][rs * 2 + 1] + __ldg(b2 + gc + 1);
                *reinterpret_cast<float2*>(out + (size_t)gm * ODIM + gc) = o2;
            }
        }
    }
}

// ---------------------------------------------------------------------------
extern "C" void kernel_launch(void* const* d_in, const int* in_sizes, int n_in,
                              void* d_out, int out_size)
{
    const float* x        = (const float*)d_in[0];
    const float* W1       = (const float*)d_in[1];
    const float* b1       = (const float*)d_in[2];
    const float* W2       = (const float*)d_in[3];
    const float* b2       = (const float*)d_in[4];
    const float* tau_mem  = (const float*)d_in[5];
    const float* tau_syn  = (const float*)d_in[6];
    const float* v_thresh = (const float*)d_in[7];
    const float* v_reset  = (const float*)d_in[8];
    const float* v0       = (const float*)d_in[9];
    const float* i0       = (const float*)d_in[10];
    const int*   tsteps   = (const int*)d_in[11];

    float* out    = (float*)d_out;
    float* spikes = out + (size_t)BDIM * ODIM;

    __half *dA1, *dB1;
    __nv_bfloat16 *dW2;
    cudaGetSymbolAddress((void**)&dA1, g_A1H);
    cudaGetSymbolAddress((void**)&dB1, g_B1H);
    cudaGetSymbolAddress((void**)&dW2, g_W2h);

    const int smem1 = 8 * AST1;              // 147456
    const int smem2 = 4 * (AST2 + BST2);     // 61440
    cudaFuncSetAttribute(gemm1_lif_kernel, cudaFuncAttributeMaxDynamicSharedMemorySize, smem1);
    cudaFuncSetAttribute(gemm2_kernel,     cudaFuncAttributeMaxDynamicSharedMemorySize, smem2);

    splitf16_kernel<<<2048, 256>>>(x,  dA1, BDIM * INDIM);
    splitf16_kernel<<<1024, 256>>>(W1, dB1, HDIM * INDIM);
    split2_kernel<<<256, 256>>>(W2, dW2, ODIM * HDIM);

    dim3 g1(HDIM / 128, BDIM / 128);   // 16 x 32 = 512 CTAs
    gemm1_lif_kernel<<<g1, 512, smem1>>>(b1, v0, i0, tau_mem, tau_syn,
                                         v_thresh, v_reset, tsteps, spikes);

    dim3 g2(ODIM / 64, BDIM / 128);    // 4 x 32 = 128 CTAs
    gemm2_kernel<<<g2, 256, smem2>>>(b2, out);
}

// round 14
// speedup vs baseline: 2.3476x; 1.1519x over previous
#include <cuda_runtime.h>
#include <cuda_bf16.h>
#include <cuda_fp16.h>
#include <cstdint>

// ---------------------------------------------------------------------------
// SimpleSNN, emulated-fp32 GEMMs on mma.sync (sm_80+ family ISA).
// GEMM1: fp16 2-split x = a1 + 2^-12*a2', W1 = b1 + 2^-12*b2'; 3 products
//   (a1b2', a2'b1, a1b1); corrections in one tensor chain drained x2^-12;
//   dominant a1b1 drained into RN fp32 masters per chunk (truncating-
//   accumulator fix, R8). R14: 128x64 tiles / 256 threads / 110.6KB smem ->
//   2 independent CTAs per SM to cross-cover barrier+cp.async stalls.
// GEMM2: bf16 (spikes exact) @ [w1|w2] 2-split; retiled 64x64, 256 CTAs.
// d_out layout: [ output (B*OUT) | total_spikes (B*H) ]
// ---------------------------------------------------------------------------

#define BDIM 4096
#define INDIM 1024
#define HDIM 2048
#define ODIM 256

__device__ __half         g_A1H[(size_t)BDIM * 2048];  // x   [a1|a2'*2^12]
__device__ __half         g_B1H[(size_t)HDIM * 2048];  // W1  [b1|b2'*2^12]
__device__ __nv_bfloat16  g_Sh [(size_t)BDIM * HDIM];  // spikes bf16 (exact)
__device__ __nv_bfloat16  g_W2h[(size_t)ODIM * 4096];  // W2  [w1|w2]

// ------------------------------ helpers ------------------------------------
__device__ __forceinline__ uint32_t smem_u32(const void* p) {
    uint32_t a;
    asm("{ .reg .u64 t; cvta.to.shared.u64 t, %1; cvt.u32.u64 %0, t; }" : "=r"(a) : "l"(p));
    return a;
}
#define CP16(dst, src)  asm volatile("cp.async.cg.shared.global [%0], [%1], 16;" :: "r"(dst), "l"(src))
#define CP_COMMIT()     asm volatile("cp.async.commit_group;" ::: "memory")
#define CP_WAIT2()      asm volatile("cp.async.wait_group 2;" ::: "memory")
#define LDSM4(R, a) asm volatile("ldmatrix.sync.aligned.m8n8.x4.shared.b16 {%0,%1,%2,%3}, [%4];" \
    : "=r"((R)[0]), "=r"((R)[1]), "=r"((R)[2]), "=r"((R)[3]) : "r"(a))

__device__ __forceinline__ void mma_f16(float* c, const uint32_t* a, const uint32_t* b) {
    asm volatile(
        "mma.sync.aligned.m16n8k16.row.col.f32.f16.f16.f32 "
        "{%0,%1,%2,%3}, {%4,%5,%6,%7}, {%8,%9}, {%0,%1,%2,%3};"
        : "+f"(c[0]), "+f"(c[1]), "+f"(c[2]), "+f"(c[3])
        : "r"(a[0]), "r"(a[1]), "r"(a[2]), "r"(a[3]), "r"(b[0]), "r"(b[1]));
}
__device__ __forceinline__ void mma_bf16(float* c, const uint32_t* a, const uint32_t* b) {
    asm volatile(
        "mma.sync.aligned.m16n8k16.row.col.f32.bf16.bf16.f32 "
        "{%0,%1,%2,%3}, {%4,%5,%6,%7}, {%8,%9}, {%0,%1,%2,%3};"
        : "+f"(c[0]), "+f"(c[1]), "+f"(c[2]), "+f"(c[3])
        : "r"(a[0]), "r"(a[1]), "r"(a[2]), "r"(a[3]), "r"(b[0]), "r"(b[1]));
}

// ------------------------------ split kernels ------------------------------
__global__ void splitf16_kernel(const float* __restrict__ src, __half* __restrict__ dst,
                                int total)  // K=1024, dst stride 2048
{
    for (int e = blockIdx.x * blockDim.x + threadIdx.x; e < total; e += gridDim.x * blockDim.x) {
        const int r = e >> 10, k = e & 1023;
        const float a = src[e];
        const __half h1 = __float2half_rn(a);
        const float rr = a - __half2float(h1);
        const __half h2 = __float2half_rn(rr * 4096.0f);
        __half* d = dst + (size_t)r * 2048;
        d[k] = h1; d[1024 + k] = h2;
    }
}
__global__ void split2_kernel(const float* __restrict__ src, __nv_bfloat16* __restrict__ dst,
                              int total)  // K=2048, dst stride 4096 (W2, bf16)
{
    for (int e = blockIdx.x * blockDim.x + threadIdx.x; e < total; e += gridDim.x * blockDim.x) {
        const int r = e >> 11, k = e & 2047;
        const float a = src[e];
        const __nv_bfloat16 a1 = __float2bfloat16(a);
        const __nv_bfloat16 a2 = __float2bfloat16(a - __bfloat162float(a1));
        __nv_bfloat16* d = dst + (size_t)r * 4096;
        d[k] = a1; d[2048 + k] = a2;
    }
}

// ------------------------------ GEMM1 + LIF --------------------------------
// CTA 128(M)x64(N), 256 threads, warp grid 4(m)x2(n), warp tile 32x32.
// BK=64 fp16 (128B rows padded to 144B), 4-stage cp.async, wait_group 2.
// smem 110.6KB -> 2 CTAs/SM. 48 chunks = 3 products x 16:
//   p0 (0-15):  a1  x b2'   } corrections, one chain, drained x2^-12 at kt=31
//   p1 (16-31): a2' x b1    }
//   p2 (32-47): a1  x b1    — drained into masters every chunk
#define G1_CHUNKS 48
#define RB1 144               // bytes per smem row
#define AST1 (128 * RB1)      // 18432 B per A stage
#define BST1 (64 * RB1)       // 9216 B per B stage

__device__ __forceinline__ void g1_load(uint32_t sA, uint32_t sB, int m0, int n0,
                                        int kt, int st, int tid)
{
    const int p = kt >> 4, cc = kt & 15;
    // A: 128 rows x 128B, 256 threads x 64B (4 cp.async)
    {
        const int row = tid >> 1, part = tid & 1;
        const int sec = (p == 1) ? 1 : 0;               // a: a1, a2', a1
        const __half* g = g_A1H + (size_t)(m0 + row) * 2048 + sec * 1024 + cc * 64 + part * 32;
        const uint32_t d = sA + st * AST1 + row * RB1 + part * 64;
        CP16(d, g); CP16(d + 16, g + 8); CP16(d + 32, g + 16); CP16(d + 48, g + 24);
    }
    // B: 64 rows x 128B, 256 threads x 32B (2 cp.async)
    {
        const int row = tid >> 2, part = tid & 3;
        const int sec = (p == 0) ? 1 : 0;               // b: b2', b1, b1
        const __half* g = g_B1H + (size_t)(n0 + row) * 2048 + sec * 1024 + cc * 64 + part * 16;
        const uint32_t d = sB + st * BST1 + row * RB1 + part * 32;
        CP16(d, g); CP16(d + 16, g + 8);
    }
}

__global__ __launch_bounds__(256, 2)
void gemm1_lif_kernel(const float* __restrict__ b1, const float* __restrict__ v0,
                      const float* __restrict__ i0, const float* __restrict__ tau_mem,
                      const float* __restrict__ tau_syn, const float* __restrict__ v_thresh,
                      const float* __restrict__ v_reset, const int* __restrict__ tsteps,
                      float* __restrict__ spikes)
{
    extern __shared__ __align__(128) char smem[];
    const uint32_t sA = smem_u32(smem);
    const uint32_t sB = sA + 4 * AST1;

    const int tid = threadIdx.x, lane = tid & 31, wid = tid >> 5;
    const int wm = wid & 3, wn = wid >> 2;             // 4(m) x 2(n), warp tile 32x32
    const int g = lane >> 2, tq = lane & 3;
    const int mi = lane >> 3, r8 = lane & 7;
    const int m0 = blockIdx.y * 128, n0 = blockIdx.x * 64;

    const uint32_t aoff = (uint32_t)(((mi & 1) * 8 + r8) * RB1 + (mi >> 1) * 16);
    const uint32_t boff = (uint32_t)(((mi >> 1) * 8 + r8) * RB1 + (mi & 1) * 16);

    float mster[2][4][4];   // RN fp32 master accumulators
    float tacc[2][4][4];    // tensor-core temp accumulators
#pragma unroll
    for (int a = 0; a < 2; a++)
#pragma unroll
        for (int b = 0; b < 4; b++)
#pragma unroll
            for (int c = 0; c < 4; c++) { mster[a][b][c] = 0.0f; tacc[a][b][c] = 0.0f; }

    g1_load(sA, sB, m0, n0, 0, 0, tid); CP_COMMIT();
    g1_load(sA, sB, m0, n0, 1, 1, tid); CP_COMMIT();
    g1_load(sA, sB, m0, n0, 2, 2, tid); CP_COMMIT();

    for (int kt = 0; kt < G1_CHUNKS; kt++) {
        const int buf = kt & 3;
        CP_WAIT2();
        __syncthreads();
        if (kt + 3 < G1_CHUNKS) g1_load(sA, sB, m0, n0, kt + 3, (kt + 3) & 3, tid);
        CP_COMMIT();

        const uint32_t Ab = sA + buf * AST1 + (wm * 32) * RB1 + aoff;
        const uint32_t Bb = sB + buf * BST1 + (wn * 32) * RB1 + boff;
#pragma unroll
        for (int ks = 0; ks < 4; ks++) {
            uint32_t af[2][4], bfr[2][4];
#pragma unroll
            for (int mt = 0; mt < 2; mt++) LDSM4(af[mt], Ab + mt * 16 * RB1 + ks * 32);
#pragma unroll
            for (int np = 0; np < 2; np++) LDSM4(bfr[np], Bb + np * 16 * RB1 + ks * 32);
#pragma unroll
            for (int mt = 0; mt < 2; mt++)
#pragma unroll
                for (int nt = 0; nt < 4; nt++)
                    mma_f16(tacc[mt][nt], af[mt], &bfr[nt >> 1][(nt & 1) * 2]);
        }
        // Drain: corrections once at kt==31 (undo 2^12 scale), then per a1b1 chunk.
        if (kt >= 31) {
            const float sc = (kt == 31) ? (1.0f / 4096.0f) : 1.0f;
#pragma unroll
            for (int a = 0; a < 2; a++)
#pragma unroll
                for (int b = 0; b < 4; b++)
#pragma unroll
                    for (int c = 0; c < 4; c++) {
                        mster[a][b][c] += tacc[a][b][c] * sc;
                        tacc[a][b][c] = 0.0f;
                    }
        }
    }
    // C frag: c0=(g,2tq) c1=(g,2tq+1) c2=(g+8,2tq) c3=(g+8,2tq+1)

    // -------------------- fused LIF epilogue --------------------
    const float km  = 1.0f / tau_mem[0];
    const float kss = 1.0f / tau_syn[0];
    const float vth = v_thresh[0];
    const float vre = v_reset[0];
    const int   T   = tsteps[0];
    const float invT = 1.0f / (float)T;

#pragma unroll
    for (int mt = 0; mt < 2; mt++) {
#pragma unroll
        for (int rs = 0; rs < 2; rs++) {
            const int gm = m0 + wm * 32 + mt * 16 + g + rs * 8;
            float cur[8], vv[8], ii[8], cnt[8];
#pragma unroll
            for (int nt = 0; nt < 4; nt++) {
                const int gc = n0 + wn * 32 + nt * 8 + 2 * tq;
                const size_t off = (size_t)gm * HDIM + gc;
                const float2 v2 = *reinterpret_cast<const float2*>(v0 + off);
                const float2 i2 = *reinterpret_cast<const float2*>(i0 + off);
                cur[2 * nt]     = (mster[mt][nt][rs * 2 + 0] + __ldg(b1 + gc))     * invT;
                cur[2 * nt + 1] = (mster[mt][nt][rs * 2 + 1] + __ldg(b1 + gc + 1)) * invT;
                vv[2 * nt] = v2.x; vv[2 * nt + 1] = v2.y;
                ii[2 * nt] = i2.x; ii[2 * nt + 1] = i2.y;
                cnt[2 * nt] = 0.0f; cnt[2 * nt + 1] = 0.0f;
            }
            for (int t = 0; t < T; t++) {
#pragma unroll
                for (int j = 0; j < 8; j++) {
                    ii[j] = ii[j] - kss * ii[j] + cur[j];
                    vv[j] = vv[j] - km  * vv[j] + ii[j];
                    if (vv[j] >= vth) { cnt[j] += 1.0f; vv[j] = vre; }
                }
            }
#pragma unroll
            for (int nt = 0; nt < 4; nt++) {
                const int gc = n0 + wn * 32 + nt * 8 + 2 * tq;
                float2 s2; s2.x = cnt[2 * nt]; s2.y = cnt[2 * nt + 1];
                *reinterpret_cast<float2*>(spikes + (size_t)gm * HDIM + gc) = s2;
                __nv_bfloat162 sb;
                sb.x = __float2bfloat16(cnt[2 * nt]);
                sb.y = __float2bfloat16(cnt[2 * nt + 1]);
                *reinterpret_cast<__nv_bfloat162*>(g_Sh + (size_t)gm * HDIM + gc) = sb;
            }
        }
    }
}

// ------------------------------ GEMM2 --------------------------------------
// out = [s|s] @ [w1|w2]^T + b2. Tile 64(M)x64(N), 256 threads, warp grid
// 4(m)x2(n), warp tile 16x32. BK=32, 4 stages, wait_group 2, 128 chunks.
// grid 256 CTAs -> ~4 co-resident CTAs/SM. Tensor-chain bias ~6e-5: fine.
#define G2_CHUNKS 128
#define AST2 5120    // 64 rows * 80B per stage
#define BST2 5120    // 64 rows * 80B per stage

__device__ __forceinline__ void g2_load(uint32_t sA, uint32_t sB, int m0, int n0,
                                        int kt, int st, int tid)
{
    const int row = tid >> 2, part = tid & 3;   // 16B per thread per matrix
    {
        const __nv_bfloat16* g = g_Sh + (size_t)(m0 + row) * HDIM + (kt & 63) * 32 + part * 8;
        const uint32_t d = sA + st * AST2 + row * 80 + part * 16;
        CP16(d, g);
    }
    {
        const __nv_bfloat16* g = g_W2h + (size_t)(n0 + row) * 4096 + kt * 32 + part * 8;
        const uint32_t d = sB + st * BST2 + row * 80 + part * 16;
        CP16(d, g);
    }
}

__global__ __launch_bounds__(256)
void gemm2_kernel(const float* __restrict__ b2, float* __restrict__ out)
{
    extern __shared__ __align__(128) char smem2[];
    const uint32_t sA = smem_u32(smem2);
    const uint32_t sB = sA + 4 * AST2;

    const int tid = threadIdx.x, lane = tid & 31, wid = tid >> 5;
    const int wm = wid & 3, wn = wid >> 2;             // 4(m) x 2(n), warp tile 16x32
    const int g = lane >> 2, tq = lane & 3;
    const int mi = lane >> 3, r8 = lane & 7;
    const int m0 = blockIdx.y * 64, n0 = blockIdx.x * 64;

    const uint32_t aoff = (uint32_t)(((mi & 1) * 8 + r8) * 80 + (mi >> 1) * 16);
    const uint32_t boff = (uint32_t)(((mi >> 1) * 8 + r8) * 80 + (mi & 1) * 16);

    float acc[4][4];
#pragma unroll
    for (int b = 0; b < 4; b++)
#pragma unroll
        for (int c = 0; c < 4; c++) acc[b][c] = 0.0f;

    g2_load(sA, sB, m0, n0, 0, 0, tid); CP_COMMIT();
    g2_load(sA, sB, m0, n0, 1, 1, tid); CP_COMMIT();
    g2_load(sA, sB, m0, n0, 2, 2, tid); CP_COMMIT();

    for (int kt = 0; kt < G2_CHUNKS; kt++) {
        const int buf = kt & 3;
        CP_WAIT2();
        __syncthreads();
        if (kt + 3 < G2_CHUNKS) g2_load(sA, sB, m0, n0, kt + 3, (kt + 3) & 3, tid);
        CP_COMMIT();

        const uint32_t Ab = sA + buf * AST2 + (wm * 16) * 80 + aoff;
        const uint32_t Bb = sB + buf * BST2 + (wn * 32) * 80 + boff;
#pragma unroll
        for (int ks = 0; ks < 2; ks++) {
            uint32_t af[4], bfr[2][4];
            LDSM4(af, Ab + ks * 32);
#pragma unroll
            for (int np = 0; np < 2; np++) LDSM4(bfr[np], Bb + np * 16 * 80 + ks * 32);
#pragma unroll
            for (int nt = 0; nt < 4; nt++)
                mma_bf16(acc[nt], af, &bfr[nt >> 1][(nt & 1) * 2]);
        }
    }

#pragma unroll
    for (int rs = 0; rs < 2; rs++) {
        const int gm = m0 + wm * 16 + g + rs * 8;
#pragma unroll
        for (int nt = 0; nt < 4; nt++) {
            const int gc = n0 + wn * 32 + nt * 8 + 2 * tq;
            float2 o2;
            o2.x = acc[nt][rs * 2 + 0] + __ldg(b2 + gc);
            o2.y = acc[nt][rs * 2 + 1] + __ldg(b2 + gc + 1);
            *reinterpret_cast<float2*>(out + (size_t)gm * ODIM + gc) = o2;
        }
    }
}

// ---------------------------------------------------------------------------
extern "C" void kernel_launch(void* const* d_in, const int* in_sizes, int n_in,
                              void* d_out, int out_size)
{
    const float* x        = (const float*)d_in[0];
    const float* W1       = (const float*)d_in[1];
    const float* b1       = (const float*)d_in[2];
    const float* W2       = (const float*)d_in[3];
    const float* b2       = (const float*)d_in[4];
    const float* tau_mem  = (const float*)d_in[5];
    const float* tau_syn  = (const float*)d_in[6];
    const float* v_thresh = (const float*)d_in[7];
    const float* v_reset  = (const float*)d_in[8];
    const float* v0       = (const float*)d_in[9];
    const float* i0       = (const float*)d_in[10];
    const int*   tsteps   = (const int*)d_in[11];

    float* out    = (float*)d_out;
    float* spikes = out + (size_t)BDIM * ODIM;

    __half *dA1, *dB1;
    __nv_bfloat16 *dW2;
    cudaGetSymbolAddress((void**)&dA1, g_A1H);
    cudaGetSymbolAddress((void**)&dB1, g_B1H);
    cudaGetSymbolAddress((void**)&dW2, g_W2h);

    const int smem1 = 4 * (AST1 + BST1);     // 110592 -> 2 CTAs/SM
    const int smem2 = 4 * (AST2 + BST2);     // 40960  -> ~4 CTAs/SM
    cudaFuncSetAttribute(gemm1_lif_kernel, cudaFuncAttributeMaxDynamicSharedMemorySize, smem1);
    cudaFuncSetAttribute(gemm2_kernel,     cudaFuncAttributeMaxDynamicSharedMemorySize, smem2);

    splitf16_kernel<<<2048, 256>>>(x,  dA1, BDIM * INDIM);
    splitf16_kernel<<<1024, 256>>>(W1, dB1, HDIM * INDIM);
    split2_kernel<<<256, 256>>>(W2, dW2, ODIM * HDIM);

    dim3 g1(HDIM / 64, BDIM / 128);    // 32 x 32 = 1024 CTAs
    gemm1_lif_kernel<<<g1, 256, smem1>>>(b1, v0, i0, tau_mem, tau_syn,
                                         v_thresh, v_reset, tsteps, spikes);

    dim3 g2(ODIM / 64, BDIM / 64);     // 4 x 64 = 256 CTAs
    gemm2_kernel<<<g2, 256, smem2>>>(b2, out);
}

// round 15
// speedup vs baseline: 2.4553x; 1.0459x over previous
#include <cuda_runtime.h>
#include <cuda_bf16.h>
#include <cuda_fp16.h>
#include <cstdint>

// ---------------------------------------------------------------------------
// SimpleSNN, emulated-fp32 GEMMs on mma.sync (sm_80+ family ISA).
// GEMM1: fp16 2-split x = a1 + 2^-12*a2', W1 = b1 + 2^-12*b2'; 3 products
//   (a1b2', a2'b1, a1b1). Corrections in one tensor chain; a1b1 drained into
//   RN fp32 masters every 2 chunks (64-k chains, R13-proven bias structure).
// R15: occupancy play — 512 thr, warp tile 32x16 (tacc=16 regs), masters in
//   SMEM (transposed, conflict-free) -> ~55 regs -> 2 CTAs x 16 warps = 50% occ.
// GEMM2: unchanged R14 (64x64, 256 CTAs, single wave).
// d_out layout: [ output (B*OUT) | total_spikes (B*H) ]
// ---------------------------------------------------------------------------

#define BDIM 4096
#define INDIM 1024
#define HDIM 2048
#define ODIM 256

__device__ __half         g_A1H[(size_t)BDIM * 2048];  // x   [a1|a2'*2^12]
__device__ __half         g_B1H[(size_t)HDIM * 2048];  // W1  [b1|b2'*2^12]
__device__ __nv_bfloat16  g_Sh [(size_t)BDIM * HDIM];  // spikes bf16 (exact)
__device__ __nv_bfloat16  g_W2h[(size_t)ODIM * 4096];  // W2  [w1|w2]

// ------------------------------ helpers ------------------------------------
__device__ __forceinline__ uint32_t smem_u32(const void* p) {
    uint32_t a;
    asm("{ .reg .u64 t; cvta.to.shared.u64 t, %1; cvt.u32.u64 %0, t; }" : "=r"(a) : "l"(p));
    return a;
}
#define CP16(dst, src)  asm volatile("cp.async.cg.shared.global [%0], [%1], 16;" :: "r"(dst), "l"(src))
#define CP_COMMIT()     asm volatile("cp.async.commit_group;" ::: "memory")
#define CP_WAIT2()      asm volatile("cp.async.wait_group 2;" ::: "memory")
#define LDSM4(R, a) asm volatile("ldmatrix.sync.aligned.m8n8.x4.shared.b16 {%0,%1,%2,%3}, [%4];" \
    : "=r"((R)[0]), "=r"((R)[1]), "=r"((R)[2]), "=r"((R)[3]) : "r"(a))

__device__ __forceinline__ void mma_f16(float* c, const uint32_t* a, const uint32_t* b) {
    asm volatile(
        "mma.sync.aligned.m16n8k16.row.col.f32.f16.f16.f32 "
        "{%0,%1,%2,%3}, {%4,%5,%6,%7}, {%8,%9}, {%0,%1,%2,%3};"
        : "+f"(c[0]), "+f"(c[1]), "+f"(c[2]), "+f"(c[3])
        : "r"(a[0]), "r"(a[1]), "r"(a[2]), "r"(a[3]), "r"(b[0]), "r"(b[1]));
}
__device__ __forceinline__ void mma_bf16(float* c, const uint32_t* a, const uint32_t* b) {
    asm volatile(
        "mma.sync.aligned.m16n8k16.row.col.f32.bf16.bf16.f32 "
        "{%0,%1,%2,%3}, {%4,%5,%6,%7}, {%8,%9}, {%0,%1,%2,%3};"
        : "+f"(c[0]), "+f"(c[1]), "+f"(c[2]), "+f"(c[3])
        : "r"(a[0]), "r"(a[1]), "r"(a[2]), "r"(a[3]), "r"(b[0]), "r"(b[1]));
}

// --------------------------- fused split kernel -----------------------------
// x, W1 -> fp16 2-split (scaled low); W2 -> bf16 2-split. One launch.
__global__ void split_all_kernel(const float* __restrict__ x,
                                 const float* __restrict__ W1,
                                 const float* __restrict__ W2)
{
    const int stride = gridDim.x * blockDim.x;
    const int t0 = blockIdx.x * blockDim.x + threadIdx.x;
    // x: [BDIM, 1024] -> g_A1H [BDIM, 2048]
    for (int e = t0; e < BDIM * INDIM; e += stride) {
        const int r = e >> 10, k = e & 1023;
        const float a = x[e];
        const __half h1 = __float2half_rn(a);
        const float rr = a - __half2float(h1);
        const __half h2 = __float2half_rn(rr * 4096.0f);
        __half* d = g_A1H + (size_t)r * 2048;
        d[k] = h1; d[1024 + k] = h2;
    }
    // W1: [HDIM, 1024] -> g_B1H
    for (int e = t0; e < HDIM * INDIM; e += stride) {
        const int r = e >> 10, k = e & 1023;
        const float a = W1[e];
        const __half h1 = __float2half_rn(a);
        const float rr = a - __half2float(h1);
        const __half h2 = __float2half_rn(rr * 4096.0f);
        __half* d = g_B1H + (size_t)r * 2048;
        d[k] = h1; d[1024 + k] = h2;
    }
    // W2: [ODIM, 2048] -> g_W2h [ODIM, 4096] bf16 2-split
    for (int e = t0; e < ODIM * HDIM; e += stride) {
        const int r = e >> 11, k = e & 2047;
        const float a = W2[e];
        const __nv_bfloat16 a1 = __float2bfloat16(a);
        const __nv_bfloat16 a2 = __float2bfloat16(a - __bfloat162float(a1));
        __nv_bfloat16* d = g_W2h + (size_t)r * 4096;
        d[k] = a1; d[2048 + k] = a2;
    }
}

// ------------------------------ GEMM1 + LIF --------------------------------
// CTA 128(M)x64(N), 512 threads, warp grid 4(m)x4(n), warp tile 32x16.
// BK=32 fp16 (64B rows padded to 80B), 4-stage cp.async, wait_group 2.
// smem: 4x(10240+5120) + 32KB masters = 94208 B -> 2 CTAs/SM, 32 warps.
// 96 chunks = 3 products x 32:
//   p0 (0-31):  a1  x b2'   } corrections, one chain, drained x2^-12 at kt=63
//   p1 (32-63): a2' x b1    }
//   p2 (64-95): a1  x b1    — drained into smem masters every 2 chunks
#define G1_CHUNKS 96
#define RB1 80                // bytes per smem row
#define AST1 (128 * RB1)      // 10240 B per A stage
#define BST1 (64 * RB1)       // 5120 B per B stage
#define SMEM1 (4 * (AST1 + BST1) + 512 * 16 * 4)   // 94208

__device__ __forceinline__ void g1_load(uint32_t sA, uint32_t sB, int m0, int n0,
                                        int kt, int st, int tid)
{
    const int p = kt >> 5, cc = kt & 31;
    // A: 128 rows x 64B; 512 threads x 16B
    {
        const int row = tid >> 2, part = tid & 3;
        const int sec = (p == 1) ? 1 : 0;               // a: a1, a2', a1
        const __half* g = g_A1H + (size_t)(m0 + row) * 2048 + sec * 1024 + cc * 32 + part * 8;
        CP16(sA + st * AST1 + row * RB1 + part * 16, g);
    }
    // B: 64 rows x 64B; first 256 threads x 16B
    if (tid < 256) {
        const int row = tid >> 2, part = tid & 3;
        const int sec = (p == 0) ? 1 : 0;               // b: b2', b1, b1
        const __half* g = g_B1H + (size_t)(n0 + row) * 2048 + sec * 1024 + cc * 32 + part * 8;
        CP16(sB + st * BST1 + row * RB1 + part * 16, g);
    }
}

__global__ __launch_bounds__(512, 2)
void gemm1_lif_kernel(const float* __restrict__ b1, const float* __restrict__ v0,
                      const float* __restrict__ i0, const float* __restrict__ tau_mem,
                      const float* __restrict__ tau_syn, const float* __restrict__ v_thresh,
                      const float* __restrict__ v_reset, const int* __restrict__ tsteps,
                      float* __restrict__ spikes)
{
    extern __shared__ __align__(128) char smem[];
    const uint32_t sA = smem_u32(smem);
    const uint32_t sB = sA + 4 * AST1;
    const uint32_t sM = sB + 4 * BST1;     // masters: [16][512] floats, transposed

    const int tid = threadIdx.x, lane = tid & 31, wid = tid >> 5;
    const int wm = wid & 3, wn = wid >> 2;             // 4(m) x 4(n), warp tile 32x16
    const int g = lane >> 2, tq = lane & 3;
    const int mi = lane >> 3, r8 = lane & 7;
    const int m0 = blockIdx.y * 128, n0 = blockIdx.x * 64;

    const uint32_t aoff = (uint32_t)(((mi & 1) * 8 + r8) * RB1 + (mi >> 1) * 16);
    const uint32_t boff = (uint32_t)(((mi >> 1) * 8 + r8) * RB1 + (mi & 1) * 16);

    float tacc[2][2][4];    // tensor-core temp accumulators (16 regs)
#pragma unroll
    for (int a = 0; a < 2; a++)
#pragma unroll
        for (int b = 0; b < 2; b++)
#pragma unroll
            for (int c = 0; c < 4; c++) tacc[a][b][c] = 0.0f;

    g1_load(sA, sB, m0, n0, 0, 0, tid); CP_COMMIT();
    g1_load(sA, sB, m0, n0, 1, 1, tid); CP_COMMIT();
    g1_load(sA, sB, m0, n0, 2, 2, tid); CP_COMMIT();

    for (int kt = 0; kt < G1_CHUNKS; kt++) {
        const int buf = kt & 3;
        CP_WAIT2();
        __syncthreads();
        if (kt + 3 < G1_CHUNKS) g1_load(sA, sB, m0, n0, kt + 3, (kt + 3) & 3, tid);
        CP_COMMIT();

        const uint32_t Ab = sA + buf * AST1 + (wm * 32) * RB1 + aoff;
        const uint32_t Bb = sB + buf * BST1 + (wn * 16) * RB1 + boff;
#pragma unroll
        for (int ks = 0; ks < 2; ks++) {
            uint32_t af[2][4], bfr[4];
            LDSM4(af[0], Ab + ks * 32);
            LDSM4(af[1], Ab + 16 * RB1 + ks * 32);
            LDSM4(bfr,   Bb + ks * 32);
#pragma unroll
            for (int mt = 0; mt < 2; mt++)
#pragma unroll
                for (int nt = 0; nt < 2; nt++)
                    mma_f16(tacc[mt][nt], af[mt], &bfr[nt * 2]);
        }
        // Drains into smem masters (transposed [16][512], conflict-free):
        //   kt==63: store corrections x 2^-12 (initializes masters)
        //   kt>63 odd: accumulate a1b1 (64-k chains)
        if (kt == 63) {
#pragma unroll
            for (int mt = 0; mt < 2; mt++)
#pragma unroll
                for (int nt = 0; nt < 2; nt++)
#pragma unroll
                    for (int c = 0; c < 4; c++) {
                        const int i = mt * 8 + nt * 4 + c;
                        const float v = tacc[mt][nt][c] * (1.0f / 4096.0f);
                        asm volatile("st.shared.f32 [%0], %1;" :: "r"(sM + i * 2048 + tid * 4), "f"(v));
                        tacc[mt][nt][c] = 0.0f;
                    }
        } else if (kt > 63 && (kt & 1)) {
#pragma unroll
            for (int mt = 0; mt < 2; mt++)
#pragma unroll
                for (int nt = 0; nt < 2; nt++)
#pragma unroll
                    for (int c = 0; c < 4; c++) {
                        const int i = mt * 8 + nt * 4 + c;
                        const uint32_t ad = sM + i * 2048 + tid * 4;
                        float v;
                        asm volatile("ld.shared.f32 %0, [%1];" : "=f"(v) : "r"(ad));
                        v += tacc[mt][nt][c];
                        asm volatile("st.shared.f32 [%0], %1;" :: "r"(ad), "f"(v));
                        tacc[mt][nt][c] = 0.0f;
                    }
        }
    }
    // C frag: c0=(g,2tq) c1=(g,2tq+1) c2=(g+8,2tq) c3=(g+8,2tq+1)

    // -------------------- fused LIF epilogue --------------------
    const float km  = 1.0f / tau_mem[0];
    const float kss = 1.0f / tau_syn[0];
    const float vth = v_thresh[0];
    const float vre = v_reset[0];
    const int   T   = tsteps[0];
    const float invT = 1.0f / (float)T;

#pragma unroll
    for (int mt = 0; mt < 2; mt++) {
#pragma unroll
        for (int rs = 0; rs < 2; rs++) {
            const int gm = m0 + wm * 32 + mt * 16 + g + rs * 8;
            float cur[4], vv[4], ii[4], cnt[4];
#pragma unroll
            for (int nt = 0; nt < 2; nt++) {
                const int gc = n0 + wn * 16 + nt * 8 + 2 * tq;
                const size_t off = (size_t)gm * HDIM + gc;
                const float2 v2 = *reinterpret_cast<const float2*>(v0 + off);
                const float2 i2 = *reinterpret_cast<const float2*>(i0 + off);
#pragma unroll
                for (int cj = 0; cj < 2; cj++) {
                    const int i = mt * 8 + nt * 4 + rs * 2 + cj;
                    float ms;
                    asm volatile("ld.shared.f32 %0, [%1];" : "=f"(ms) : "r"(sM + i * 2048 + tid * 4));
                    cur[2 * nt + cj] = (ms + __ldg(b1 + gc + cj)) * invT;
                }
                vv[2 * nt] = v2.x; vv[2 * nt + 1] = v2.y;
                ii[2 * nt] = i2.x; ii[2 * nt + 1] = i2.y;
                cnt[2 * nt] = 0.0f; cnt[2 * nt + 1] = 0.0f;
            }
            for (int t = 0; t < T; t++) {
#pragma unroll
                for (int j = 0; j < 4; j++) {
                    ii[j] = ii[j] - kss * ii[j] + cur[j];
                    vv[j] = vv[j] - km  * vv[j] + ii[j];
                    if (vv[j] >= vth) { cnt[j] += 1.0f; vv[j] = vre; }
                }
            }
#pragma unroll
            for (int nt = 0; nt < 2; nt++) {
                const int gc = n0 + wn * 16 + nt * 8 + 2 * tq;
                float2 s2; s2.x = cnt[2 * nt]; s2.y = cnt[2 * nt + 1];
                *reinterpret_cast<float2*>(spikes + (size_t)gm * HDIM + gc) = s2;
                __nv_bfloat162 sb;
                sb.x = __float2bfloat16(cnt[2 * nt]);
                sb.y = __float2bfloat16(cnt[2 * nt + 1]);
                *reinterpret_cast<__nv_bfloat162*>(g_Sh + (size_t)gm * HDIM + gc) = sb;
            }
        }
    }
}

// ------------------------------ GEMM2 --------------------------------------
// out = [s|s] @ [w1|w2]^T + b2. Tile 64(M)x64(N), 256 threads, warp grid
// 4(m)x2(n), warp tile 16x32. BK=32, 4 stages, wait_group 2, 128 chunks.
// grid 256 CTAs -> ~4 co-resident CTAs/SM, single wave.
#define G2_CHUNKS 128
#define AST2 5120    // 64 rows * 80B per stage
#define BST2 5120    // 64 rows * 80B per stage

__device__ __forceinline__ void g2_load(uint32_t sA, uint32_t sB, int m0, int n0,
                                        int kt, int st, int tid)
{
    const int row = tid >> 2, part = tid & 3;   // 16B per thread per matrix
    {
        const __nv_bfloat16* g = g_Sh + (size_t)(m0 + row) * HDIM + (kt & 63) * 32 + part * 8;
        CP16(sA + st * AST2 + row * 80 + part * 16, g);
    }
    {
        const __nv_bfloat16* g = g_W2h + (size_t)(n0 + row) * 4096 + kt * 32 + part * 8;
        CP16(sB + st * BST2 + row * 80 + part * 16, g);
    }
}

__global__ __launch_bounds__(256)
void gemm2_kernel(const float* __restrict__ b2, float* __restrict__ out)
{
    extern __shared__ __align__(128) char smem2[];
    const uint32_t sA = smem_u32(smem2);
    const uint32_t sB = sA + 4 * AST2;

    const int tid = threadIdx.x, lane = tid & 31, wid = tid >> 5;
    const int wm = wid & 3, wn = wid >> 2;             // 4(m) x 2(n), warp tile 16x32
    const int g = lane >> 2, tq = lane & 3;
    const int mi = lane >> 3, r8 = lane & 7;
    const int m0 = blockIdx.y * 64, n0 = blockIdx.x * 64;

    const uint32_t aoff = (uint32_t)(((mi & 1) * 8 + r8) * 80 + (mi >> 1) * 16);
    const uint32_t boff = (uint32_t)(((mi >> 1) * 8 + r8) * 80 + (mi & 1) * 16);

    float acc[4][4];
#pragma unroll
    for (int b = 0; b < 4; b++)
#pragma unroll
        for (int c = 0; c < 4; c++) acc[b][c] = 0.0f;

    g2_load(sA, sB, m0, n0, 0, 0, tid); CP_COMMIT();
    g2_load(sA, sB, m0, n0, 1, 1, tid); CP_COMMIT();
    g2_load(sA, sB, m0, n0, 2, 2, tid); CP_COMMIT();

    for (int kt = 0; kt < G2_CHUNKS; kt++) {
        const int buf = kt & 3;
        CP_WAIT2();
        __syncthreads();
        if (kt + 3 < G2_CHUNKS) g2_load(sA, sB, m0, n0, kt + 3, (kt + 3) & 3, tid);
        CP_COMMIT();

        const uint32_t Ab = sA + buf * AST2 + (wm * 16) * 80 + aoff;
        const uint32_t Bb = sB + buf * BST2 + (wn * 32) * 80 + boff;
#pragma unroll
        for (int ks = 0; ks < 2; ks++) {
            uint32_t af[4], bfr[2][4];
            LDSM4(af, Ab + ks * 32);
#pragma unroll
            for (int np = 0; np < 2; np++) LDSM4(bfr[np], Bb + np * 16 * 80 + ks * 32);
#pragma unroll
            for (int nt = 0; nt < 4; nt++)
                mma_bf16(acc[nt], af, &bfr[nt >> 1][(nt & 1) * 2]);
        }
    }

#pragma unroll
    for (int rs = 0; rs < 2; rs++) {
        const int gm = m0 + wm * 16 + g + rs * 8;
#pragma unroll
        for (int nt = 0; nt < 4; nt++) {
            const int gc = n0 + wn * 32 + nt * 8 + 2 * tq;
            float2 o2;
            o2.x = acc[nt][rs * 2 + 0] + __ldg(b2 + gc);
            o2.y = acc[nt][rs * 2 + 1] + __ldg(b2 + gc + 1);
            *reinterpret_cast<float2*>(out + (size_t)gm * ODIM + gc) = o2;
        }
    }
}

// ---------------------------------------------------------------------------
extern "C" void kernel_launch(void* const* d_in, const int* in_sizes, int n_in,
                              void* d_out, int out_size)
{
    const float* x        = (const float*)d_in[0];
    const float* W1       = (const float*)d_in[1];
    const float* b1       = (const float*)d_in[2];
    const float* W2       = (const float*)d_in[3];
    const float* b2       = (const float*)d_in[4];
    const float* tau_mem  = (const float*)d_in[5];
    const float* tau_syn  = (const float*)d_in[6];
    const float* v_thresh = (const float*)d_in[7];
    const float* v_reset  = (const float*)d_in[8];
    const float* v0       = (const float*)d_in[9];
    const float* i0       = (const float*)d_in[10];
    const int*   tsteps   = (const int*)d_in[11];

    float* out    = (float*)d_out;
    float* spikes = out + (size_t)BDIM * ODIM;

    const int smem2 = 4 * (AST2 + BST2);     // 40960  -> ~4 CTAs/SM
    cudaFuncSetAttribute(gemm1_lif_kernel, cudaFuncAttributeMaxDynamicSharedMemorySize, SMEM1);
    cudaFuncSetAttribute(gemm2_kernel,     cudaFuncAttributeMaxDynamicSharedMemorySize, smem2);

    split_all_kernel<<<2048, 256>>>(x, W1, W2);

    dim3 g1(HDIM / 64, BDIM / 128);    // 32 x 32 = 1024 CTAs
    gemm1_lif_kernel<<<g1, 512, SMEM1>>>(b1, v0, i0, tau_mem, tau_syn,
                                         v_thresh, v_reset, tsteps, spikes);

    dim3 g2(ODIM / 64, BDIM / 64);     // 4 x 64 = 256 CTAs
    gemm2_kernel<<<g2, 256, smem2>>>(b2, out);
}

// round 16
// speedup vs baseline: 2.6106x; 1.0632x over previous
#include <cuda_runtime.h>
#include <cuda_bf16.h>
#include <cuda_fp16.h>
#include <cstdint>

// ---------------------------------------------------------------------------
// SimpleSNN, emulated-fp32 GEMMs on mma.sync (sm_80+ family ISA).
// GEMM1 (R15, at the legacy-HMMA wall ~170 TF/s): fp16 2-split
//   x = a1 + 2^-12*a2', W1 = b1 + 2^-12*b2'; products a1b2', a2'b1, a1b1;
//   corrections in one tensor chain (drained x2^-12 at kt=63); a1b1 drained
//   into SMEM fp32 masters every 2 chunks. 512 thr, warp tile 32x16, 2 CTA/SM.
// GEMM2 (R16): SINGLE fp16 product — spikes are exact fp16 ints, W2 fp16
//   rounding ~1e-4 on output (tolerance 1e-3, no threshold amplification).
//   Halves gemm2 MMA work; spikes stored fp16.
// d_out layout: [ output (B*OUT) | total_spikes (B*H) ]
// ---------------------------------------------------------------------------

#define BDIM 4096
#define INDIM 1024
#define HDIM 2048
#define ODIM 256

__device__ __half g_A1H[(size_t)BDIM * 2048];  // x   [a1|a2'*2^12]
__device__ __half g_B1H[(size_t)HDIM * 2048];  // W1  [b1|b2'*2^12]
__device__ __half g_SH [(size_t)BDIM * HDIM];  // spikes fp16 (exact)
__device__ __half g_W2H[(size_t)ODIM * HDIM];  // W2  fp16 (single)

// ------------------------------ helpers ------------------------------------
__device__ __forceinline__ uint32_t smem_u32(const void* p) {
    uint32_t a;
    asm("{ .reg .u64 t; cvta.to.shared.u64 t, %1; cvt.u32.u64 %0, t; }" : "=r"(a) : "l"(p));
    return a;
}
#define CP16(dst, src)  asm volatile("cp.async.cg.shared.global [%0], [%1], 16;" :: "r"(dst), "l"(src))
#define CP_COMMIT()     asm volatile("cp.async.commit_group;" ::: "memory")
#define CP_WAIT2()      asm volatile("cp.async.wait_group 2;" ::: "memory")
#define LDSM4(R, a) asm volatile("ldmatrix.sync.aligned.m8n8.x4.shared.b16 {%0,%1,%2,%3}, [%4];" \
    : "=r"((R)[0]), "=r"((R)[1]), "=r"((R)[2]), "=r"((R)[3]) : "r"(a))

__device__ __forceinline__ void mma_f16(float* c, const uint32_t* a, const uint32_t* b) {
    asm volatile(
        "mma.sync.aligned.m16n8k16.row.col.f32.f16.f16.f32 "
        "{%0,%1,%2,%3}, {%4,%5,%6,%7}, {%8,%9}, {%0,%1,%2,%3};"
        : "+f"(c[0]), "+f"(c[1]), "+f"(c[2]), "+f"(c[3])
        : "r"(a[0]), "r"(a[1]), "r"(a[2]), "r"(a[3]), "r"(b[0]), "r"(b[1]));
}

// --------------------------- fused split kernel -----------------------------
__global__ void split_all_kernel(const float* __restrict__ x,
                                 const float* __restrict__ W1,
                                 const float* __restrict__ W2)
{
    const int stride = gridDim.x * blockDim.x;
    const int t0 = blockIdx.x * blockDim.x + threadIdx.x;
    // x: [BDIM, 1024] -> g_A1H [BDIM, 2048] fp16 2-split (scaled low)
    for (int e = t0; e < BDIM * INDIM; e += stride) {
        const int r = e >> 10, k = e & 1023;
        const float a = x[e];
        const __half h1 = __float2half_rn(a);
        const float rr = a - __half2float(h1);
        const __half h2 = __float2half_rn(rr * 4096.0f);
        __half* d = g_A1H + (size_t)r * 2048;
        d[k] = h1; d[1024 + k] = h2;
    }
    // W1: [HDIM, 1024] -> g_B1H
    for (int e = t0; e < HDIM * INDIM; e += stride) {
        const int r = e >> 10, k = e & 1023;
        const float a = W1[e];
        const __half h1 = __float2half_rn(a);
        const float rr = a - __half2float(h1);
        const __half h2 = __float2half_rn(rr * 4096.0f);
        __half* d = g_B1H + (size_t)r * 2048;
        d[k] = h1; d[1024 + k] = h2;
    }
    // W2: [ODIM, 2048] -> g_W2H fp16 single (rounding ~1e-4 on output: OK)
    for (int e = t0; e < ODIM * HDIM; e += stride)
        g_W2H[e] = __float2half_rn(W2[e]);
}

// ------------------------------ GEMM1 + LIF --------------------------------
// CTA 128(M)x64(N), 512 threads, warp grid 4(m)x4(n), warp tile 32x16.
// BK=32 fp16 (64B rows padded to 80B), 4-stage cp.async, wait_group 2.
// smem: 4x(10240+5120) + 32KB masters = 94208 B -> 2 CTAs/SM, 32 warps.
// 96 chunks = 3 products x 32:
//   p0 (0-31):  a1  x b2'   } corrections, one chain, drained x2^-12 at kt=63
//   p1 (32-63): a2' x b1    }
//   p2 (64-95): a1  x b1    — drained into smem masters every 2 chunks
#define G1_CHUNKS 96
#define RB1 80                // bytes per smem row
#define AST1 (128 * RB1)      // 10240 B per A stage
#define BST1 (64 * RB1)       // 5120 B per B stage
#define SMEM1 (4 * (AST1 + BST1) + 512 * 16 * 4)   // 94208

__device__ __forceinline__ void g1_load(uint32_t sA, uint32_t sB, int m0, int n0,
                                        int kt, int st, int tid)
{
    const int p = kt >> 5, cc = kt & 31;
    // A: 128 rows x 64B; 512 threads x 16B
    {
        const int row = tid >> 2, part = tid & 3;
        const int sec = (p == 1) ? 1 : 0;               // a: a1, a2', a1
        const __half* g = g_A1H + (size_t)(m0 + row) * 2048 + sec * 1024 + cc * 32 + part * 8;
        CP16(sA + st * AST1 + row * RB1 + part * 16, g);
    }
    // B: 64 rows x 64B; first 256 threads x 16B
    if (tid < 256) {
        const int row = tid >> 2, part = tid & 3;
        const int sec = (p == 0) ? 1 : 0;               // b: b2', b1, b1
        const __half* g = g_B1H + (size_t)(n0 + row) * 2048 + sec * 1024 + cc * 32 + part * 8;
        CP16(sB + st * BST1 + row * RB1 + part * 16, g);
    }
}

__global__ __launch_bounds__(512, 2)
void gemm1_lif_kernel(const float* __restrict__ b1, const float* __restrict__ v0,
                      const float* __restrict__ i0, const float* __restrict__ tau_mem,
                      const float* __restrict__ tau_syn, const float* __restrict__ v_thresh,
                      const float* __restrict__ v_reset, const int* __restrict__ tsteps,
                      float* __restrict__ spikes)
{
    extern __shared__ __align__(128) char smem[];
    const uint32_t sA = smem_u32(smem);
    const uint32_t sB = sA + 4 * AST1;
    const uint32_t sM = sB + 4 * BST1;     // masters: [16][512] floats, transposed

    const int tid = threadIdx.x, lane = tid & 31, wid = tid >> 5;
    const int wm = wid & 3, wn = wid >> 2;             // 4(m) x 4(n), warp tile 32x16
    const int g = lane >> 2, tq = lane & 3;
    const int mi = lane >> 3, r8 = lane & 7;
    const int m0 = blockIdx.y * 128, n0 = blockIdx.x * 64;

    const uint32_t aoff = (uint32_t)(((mi & 1) * 8 + r8) * RB1 + (mi >> 1) * 16);
    const uint32_t boff = (uint32_t)(((mi >> 1) * 8 + r8) * RB1 + (mi & 1) * 16);

    float tacc[2][2][4];    // tensor-core temp accumulators (16 regs)
#pragma unroll
    for (int a = 0; a < 2; a++)
#pragma unroll
        for (int b = 0; b < 2; b++)
#pragma unroll
            for (int c = 0; c < 4; c++) tacc[a][b][c] = 0.0f;

    g1_load(sA, sB, m0, n0, 0, 0, tid); CP_COMMIT();
    g1_load(sA, sB, m0, n0, 1, 1, tid); CP_COMMIT();
    g1_load(sA, sB, m0, n0, 2, 2, tid); CP_COMMIT();

    for (int kt = 0; kt < G1_CHUNKS; kt++) {
        const int buf = kt & 3;
        CP_WAIT2();
        __syncthreads();
        if (kt + 3 < G1_CHUNKS) g1_load(sA, sB, m0, n0, kt + 3, (kt + 3) & 3, tid);
        CP_COMMIT();

        const uint32_t Ab = sA + buf * AST1 + (wm * 32) * RB1 + aoff;
        const uint32_t Bb = sB + buf * BST1 + (wn * 16) * RB1 + boff;
#pragma unroll
        for (int ks = 0; ks < 2; ks++) {
            uint32_t af[2][4], bfr[4];
            LDSM4(af[0], Ab + ks * 32);
            LDSM4(af[1], Ab + 16 * RB1 + ks * 32);
            LDSM4(bfr,   Bb + ks * 32);
#pragma unroll
            for (int mt = 0; mt < 2; mt++)
#pragma unroll
                for (int nt = 0; nt < 2; nt++)
                    mma_f16(tacc[mt][nt], af[mt], &bfr[nt * 2]);
        }
        // Drains into smem masters (transposed [16][512], conflict-free):
        //   kt==63: store corrections x 2^-12 (initializes masters)
        //   kt>63 odd: accumulate a1b1 (64-k chains)
        if (kt == 63) {
#pragma unroll
            for (int mt = 0; mt < 2; mt++)
#pragma unroll
                for (int nt = 0; nt < 2; nt++)
#pragma unroll
                    for (int c = 0; c < 4; c++) {
                        const int i = mt * 8 + nt * 4 + c;
                        const float v = tacc[mt][nt][c] * (1.0f / 4096.0f);
                        asm volatile("st.shared.f32 [%0], %1;" :: "r"(sM + i * 2048 + tid * 4), "f"(v));
                        tacc[mt][nt][c] = 0.0f;
                    }
        } else if (kt > 63 && (kt & 1)) {
#pragma unroll
            for (int mt = 0; mt < 2; mt++)
#pragma unroll
                for (int nt = 0; nt < 2; nt++)
#pragma unroll
                    for (int c = 0; c < 4; c++) {
                        const int i = mt * 8 + nt * 4 + c;
                        const uint32_t ad = sM + i * 2048 + tid * 4;
                        float v;
                        asm volatile("ld.shared.f32 %0, [%1];" : "=f"(v) : "r"(ad));
                        v += tacc[mt][nt][c];
                        asm volatile("st.shared.f32 [%0], %1;" :: "r"(ad), "f"(v));
                        tacc[mt][nt][c] = 0.0f;
                    }
        }
    }
    // C frag: c0=(g,2tq) c1=(g,2tq+1) c2=(g+8,2tq) c3=(g+8,2tq+1)

    // -------------------- fused LIF epilogue --------------------
    const float km  = 1.0f / tau_mem[0];
    const float kss = 1.0f / tau_syn[0];
    const float vth = v_thresh[0];
    const float vre = v_reset[0];
    const int   T   = tsteps[0];
    const float invT = 1.0f / (float)T;

#pragma unroll
    for (int mt = 0; mt < 2; mt++) {
#pragma unroll
        for (int rs = 0; rs < 2; rs++) {
            const int gm = m0 + wm * 32 + mt * 16 + g + rs * 8;
            float cur[4], vv[4], ii[4], cnt[4];
#pragma unroll
            for (int nt = 0; nt < 2; nt++) {
                const int gc = n0 + wn * 16 + nt * 8 + 2 * tq;
                const size_t off = (size_t)gm * HDIM + gc;
                const float2 v2 = *reinterpret_cast<const float2*>(v0 + off);
                const float2 i2 = *reinterpret_cast<const float2*>(i0 + off);
#pragma unroll
                for (int cj = 0; cj < 2; cj++) {
                    const int i = mt * 8 + nt * 4 + rs * 2 + cj;
                    float ms;
                    asm volatile("ld.shared.f32 %0, [%1];" : "=f"(ms) : "r"(sM + i * 2048 + tid * 4));
                    cur[2 * nt + cj] = (ms + __ldg(b1 + gc + cj)) * invT;
                }
                vv[2 * nt] = v2.x; vv[2 * nt + 1] = v2.y;
                ii[2 * nt] = i2.x; ii[2 * nt + 1] = i2.y;
                cnt[2 * nt] = 0.0f; cnt[2 * nt + 1] = 0.0f;
            }
            for (int t = 0; t < T; t++) {
#pragma unroll
                for (int j = 0; j < 4; j++) {
                    ii[j] = ii[j] - kss * ii[j] + cur[j];
                    vv[j] = vv[j] - km  * vv[j] + ii[j];
                    if (vv[j] >= vth) { cnt[j] += 1.0f; vv[j] = vre; }
                }
            }
#pragma unroll
            for (int nt = 0; nt < 2; nt++) {
                const int gc = n0 + wn * 16 + nt * 8 + 2 * tq;
                float2 s2; s2.x = cnt[2 * nt]; s2.y = cnt[2 * nt + 1];
                *reinterpret_cast<float2*>(spikes + (size_t)gm * HDIM + gc) = s2;
                __half2 sh;
                sh.x = __float2half_rn(cnt[2 * nt]);       // exact: small ints
                sh.y = __float2half_rn(cnt[2 * nt + 1]);
                *reinterpret_cast<__half2*>(g_SH + (size_t)gm * HDIM + gc) = sh;
            }
        }
    }
}

// ------------------------------ GEMM2 --------------------------------------
// out = spikes_fp16 @ W2_fp16^T + b2 (SINGLE product, K=2048, 64 chunks).
// Tile 64(M)x64(N), 256 threads, warp grid 4(m)x2(n), warp tile 16x32.
// BK=32, 4 stages, wait_group 2. grid 256 CTAs -> ~4 CTAs/SM, single wave.
#define G2_CHUNKS 64
#define AST2 5120    // 64 rows * 80B per stage
#define BST2 5120    // 64 rows * 80B per stage

__device__ __forceinline__ void g2_load(uint32_t sA, uint32_t sB, int m0, int n0,
                                        int kt, int st, int tid)
{
    const int row = tid >> 2, part = tid & 3;   // 16B per thread per matrix
    {
        const __half* g = g_SH + (size_t)(m0 + row) * HDIM + kt * 32 + part * 8;
        CP16(sA + st * AST2 + row * 80 + part * 16, g);
    }
    {
        const __half* g = g_W2H + (size_t)(n0 + row) * HDIM + kt * 32 + part * 8;
        CP16(sB + st * BST2 + row * 80 + part * 16, g);
    }
}

__global__ __launch_bounds__(256)
void gemm2_kernel(const float* __restrict__ b2, float* __restrict__ out)
{
    extern __shared__ __align__(128) char smem2[];
    const uint32_t sA = smem_u32(smem2);
    const uint32_t sB = sA + 4 * AST2;

    const int tid = threadIdx.x, lane = tid & 31, wid = tid >> 5;
    const int wm = wid & 3, wn = wid >> 2;             // 4(m) x 2(n), warp tile 16x32
    const int g = lane >> 2, tq = lane & 3;
    const int mi = lane >> 3, r8 = lane & 7;
    const int m0 = blockIdx.y * 64, n0 = blockIdx.x * 64;

    const uint32_t aoff = (uint32_t)(((mi & 1) * 8 + r8) * 80 + (mi >> 1) * 16);
    const uint32_t boff = (uint32_t)(((mi >> 1) * 8 + r8) * 80 + (mi & 1) * 16);

    float acc[4][4];
#pragma unroll
    for (int b = 0; b < 4; b++)
#pragma unroll
        for (int c = 0; c < 4; c++) acc[b][c] = 0.0f;

    g2_load(sA, sB, m0, n0, 0, 0, tid); CP_COMMIT();
    g2_load(sA, sB, m0, n0, 1, 1, tid); CP_COMMIT();
    g2_load(sA, sB, m0, n0, 2, 2, tid); CP_COMMIT();

    for (int kt = 0; kt < G2_CHUNKS; kt++) {
        const int buf = kt & 3;
        CP_WAIT2();
        __syncthreads();
        if (kt + 3 < G2_CHUNKS) g2_load(sA, sB, m0, n0, kt + 3, (kt + 3) & 3, tid);
        CP_COMMIT();

        const uint32_t Ab = sA + buf * AST2 + (wm * 16) * 80 + aoff;
        const uint32_t Bb = sB + buf * BST2 + (wn * 32) * 80 + boff;
#pragma unroll
        for (int ks = 0; ks < 2; ks++) {
            uint32_t af[4], bfr[2][4];
            LDSM4(af, Ab + ks * 32);
#pragma unroll
            for (int np = 0; np < 2; np++) LDSM4(bfr[np], Bb + np * 16 * 80 + ks * 32);
#pragma unroll
            for (int nt = 0; nt < 4; nt++)
                mma_f16(acc[nt], af, &bfr[nt >> 1][(nt & 1) * 2]);
        }
    }

#pragma unroll
    for (int rs = 0; rs < 2; rs++) {
        const int gm = m0 + wm * 16 + g + rs * 8;
#pragma unroll
        for (int nt = 0; nt < 4; nt++) {
            const int gc = n0 + wn * 32 + nt * 8 + 2 * tq;
            float2 o2;
            o2.x = acc[nt][rs * 2 + 0] + __ldg(b2 + gc);
            o2.y = acc[nt][rs * 2 + 1] + __ldg(b2 + gc + 1);
            *reinterpret_cast<float2*>(out + (size_t)gm * ODIM + gc) = o2;
        }
    }
}

// ---------------------------------------------------------------------------
extern "C" void kernel_launch(void* const* d_in, const int* in_sizes, int n_in,
                              void* d_out, int out_size)
{
    const float* x        = (const float*)d_in[0];
    const float* W1       = (const float*)d_in[1];
    const float* b1       = (const float*)d_in[2];
    const float* W2       = (const float*)d_in[3];
    const float* b2       = (const float*)d_in[4];
    const float* tau_mem  = (const float*)d_in[5];
    const float* tau_syn  = (const float*)d_in[6];
    const float* v_thresh = (const float*)d_in[7];
    const float* v_reset  = (const float*)d_in[8];
    const float* v0       = (const float*)d_in[9];
    const float* i0       = (const float*)d_in[10];
    const int*   tsteps   = (const int*)d_in[11];

    float* out    = (float*)d_out;
    float* spikes = out + (size_t)BDIM * ODIM;

    const int smem2 = 4 * (AST2 + BST2);     // 40960  -> ~4 CTAs/SM
    cudaFuncSetAttribute(gemm1_lif_kernel, cudaFuncAttributeMaxDynamicSharedMemorySize, SMEM1);
    cudaFuncSetAttribute(gemm2_kernel,     cudaFuncAttributeMaxDynamicSharedMemorySize, smem2);

    split_all_kernel<<<2048, 256>>>(x, W1, W2);

    dim3 g1(HDIM / 64, BDIM / 128);    // 32 x 32 = 1024 CTAs
    gemm1_lif_kernel<<<g1, 512, SMEM1>>>(b1, v0, i0, tau_mem, tau_syn,
                                         v_thresh, v_reset, tsteps, spikes);

    dim3 g2(ODIM / 64, BDIM / 64);     // 4 x 64 = 256 CTAs
    gemm2_kernel<<<g2, 256, smem2>>>(b2, out);
}